// round 3
// baseline (speedup 1.0000x reference)
#include <cuda_runtime.h>
#include <math.h>

#define BB 4
#define TT 1024
#define EE 1024
#define HH 16
#define DD 64
#define E3 3072
#define MTOK (BB*TT)   // 4096

// Scratch: qkv split as [3][B][H][T][D] per stream, attention outputs as (B,T,E)
__device__ float g_s1[3ull * BB * HH * TT * DD];
__device__ float g_s2[3ull * BB * HH * TT * DD];
__device__ float g_xo[(size_t)MTOK * EE];
__device__ float g_yo[(size_t)MTOK * EE];

// ---------------------------------------------------------------------------
// C = A (M,K) @ B^T where B is (N,K) row-major. 128x128 tile, 8x8 micro.
// SPLIT=true routes the output element (m,n) into [kk][b][h][t][dd] layout.
// ---------------------------------------------------------------------------
template<bool SPLIT>
__global__ void __launch_bounds__(256) gemm_abT_kernel(
    const float* __restrict__ A, const float* __restrict__ Bm,
    float* __restrict__ C, int M, int N, int K)
{
    __shared__ float As[8][128];
    __shared__ float Bs[8][128];

    const int tid = threadIdx.x;
    const int tx  = tid & 15;
    const int ty  = tid >> 4;
    const int row0 = blockIdx.y * 128;
    const int col0 = blockIdx.x * 128;

    const int lr = tid >> 1;        // 0..127
    const int lk = (tid & 1) * 4;   // 0 or 4

    float acc[8][8];
    #pragma unroll
    for (int i = 0; i < 8; ++i)
        #pragma unroll
        for (int j = 0; j < 8; ++j) acc[i][j] = 0.f;

    const float* Ag = A  + (size_t)(row0 + lr) * K + lk;
    const float* Bg = Bm + (size_t)(col0 + lr) * K + lk;

    for (int k0 = 0; k0 < K; k0 += 8) {
        float4 a = *(const float4*)(Ag + k0);
        float4 b = *(const float4*)(Bg + k0);
        __syncthreads();
        As[lk+0][lr] = a.x; As[lk+1][lr] = a.y; As[lk+2][lr] = a.z; As[lk+3][lr] = a.w;
        Bs[lk+0][lr] = b.x; Bs[lk+1][lr] = b.y; Bs[lk+2][lr] = b.z; Bs[lk+3][lr] = b.w;
        __syncthreads();

        #pragma unroll
        for (int k = 0; k < 8; ++k) {
            float4 a0 = *(const float4*)&As[k][ty * 8];
            float4 a1 = *(const float4*)&As[k][ty * 8 + 4];
            float4 b0 = *(const float4*)&Bs[k][tx * 8];
            float4 b1 = *(const float4*)&Bs[k][tx * 8 + 4];
            float ar[8] = {a0.x,a0.y,a0.z,a0.w,a1.x,a1.y,a1.z,a1.w};
            float br[8] = {b0.x,b0.y,b0.z,b0.w,b1.x,b1.y,b1.z,b1.w};
            #pragma unroll
            for (int i = 0; i < 8; ++i)
                #pragma unroll
                for (int j = 0; j < 8; ++j)
                    acc[i][j] = fmaf(ar[i], br[j], acc[i][j]);
        }
    }

    #pragma unroll
    for (int i = 0; i < 8; ++i) {
        const int m = row0 + ty * 8 + i;
        #pragma unroll
        for (int j = 0; j < 8; ++j) {
            const int n = col0 + tx * 8 + j;
            if (SPLIT) {
                // n = dd*48 + kk*16 + h ; m = b*T + t
                const int dd = n / 48;
                const int r  = n - dd * 48;
                const int kk = r >> 4;
                const int hh = r & 15;
                const int bb = m >> 10;
                const int t  = m & 1023;
                C[((((size_t)kk * BB + bb) * HH + hh) * TT + t) * DD + dd] = acc[i][j];
            } else {
                C[(size_t)m * N + n] = acc[i][j];
            }
        }
    }
}

// ---------------------------------------------------------------------------
// Dual-stream cross attention, fp32 flash style.
// s1/s2: [3][B][H][T][D].  Stream z=0: Q from s2, K/V from s1 -> xo.
//                          Stream z=1: Q from s1, K/V from s2 -> yo.
// Output layout (B, T, H*D).
// ---------------------------------------------------------------------------
__global__ void __launch_bounds__(256) cross_attn_kernel(
    const float* __restrict__ s1, const float* __restrict__ s2,
    float* __restrict__ xo, float* __restrict__ yo)
{
    extern __shared__ float sm[];
    float* Qs = sm;                  // [64][65]
    float* Ks = sm + 64 * 65;
    float* Vs = sm + 2 * 64 * 65;
    float* Ps = sm + 3 * 64 * 65;

    const int tid = threadIdx.x;
    const int tx  = tid & 15;
    const int ty  = tid >> 4;
    const int qt  = blockIdx.x;          // 0..15
    const int b   = blockIdx.y >> 4;
    const int h   = blockIdx.y & 15;
    const int st  = blockIdx.z;          // 0: xo, 1: yo

    const float* Qg = (st == 0) ? s2 : s1;
    const float* Kg = (st == 0) ? s1 : s2;
    float*       Og = (st == 0) ? xo : yo;

    const size_t plane  = (size_t)BB * HH * TT * DD;
    const size_t bhBase = ((size_t)b * HH + h) * TT * DD;
    const float* Qbase = Qg + bhBase + (size_t)qt * 64 * DD;   // kk=0
    const float* Kbase = Kg + plane     + bhBase;              // kk=1
    const float* Vbase = Kg + 2 * plane + bhBase;              // kk=2

    for (int i = tid; i < 64 * 64; i += 256) {
        const int r = i >> 6, c = i & 63;
        Qs[r * 65 + c] = Qbase[i];
    }

    float oacc[4][4];
    #pragma unroll
    for (int i = 0; i < 4; ++i)
        #pragma unroll
        for (int j = 0; j < 4; ++j) oacc[i][j] = 0.f;
    float mrow[4], lrow[4];
    #pragma unroll
    for (int i = 0; i < 4; ++i) { mrow[i] = -1e30f; lrow[i] = 0.f; }

    const int r0 = ty * 4;
    const int c0 = tx * 4;

    for (int kt = 0; kt < TT / 64; ++kt) {
        __syncthreads();   // protect smem from previous iteration's readers
        const float* kb = Kbase + (size_t)kt * 64 * DD;
        const float* vb = Vbase + (size_t)kt * 64 * DD;
        for (int i = tid; i < 64 * 64; i += 256) {
            const int r = i >> 6, c = i & 63;
            Ks[r * 65 + c] = kb[i];
            Vs[r * 65 + c] = vb[i];
        }
        __syncthreads();

        // S = (Q K^T) / 8
        float sacc[4][4];
        #pragma unroll
        for (int i = 0; i < 4; ++i)
            #pragma unroll
            for (int j = 0; j < 4; ++j) sacc[i][j] = 0.f;

        #pragma unroll 8
        for (int k = 0; k < 64; ++k) {
            float qv[4], kv[4];
            #pragma unroll
            for (int i = 0; i < 4; ++i) qv[i] = Qs[(r0 + i) * 65 + k];
            #pragma unroll
            for (int j = 0; j < 4; ++j) kv[j] = Ks[(c0 + j) * 65 + k];
            #pragma unroll
            for (int i = 0; i < 4; ++i)
                #pragma unroll
                for (int j = 0; j < 4; ++j)
                    sacc[i][j] = fmaf(qv[i], kv[j], sacc[i][j]);
        }

        // online softmax (rows split across 16 tx lanes, contiguous 16-lane group)
        #pragma unroll
        for (int i = 0; i < 4; ++i) {
            float tm = -1e30f;
            #pragma unroll
            for (int j = 0; j < 4; ++j) {
                sacc[i][j] *= 0.125f;
                tm = fmaxf(tm, sacc[i][j]);
            }
            #pragma unroll
            for (int off = 8; off >= 1; off >>= 1)
                tm = fmaxf(tm, __shfl_xor_sync(0xffffffffu, tm, off));
            const float newm = fmaxf(mrow[i], tm);
            float rs = 0.f;
            #pragma unroll
            for (int j = 0; j < 4; ++j) {
                const float p = __expf(sacc[i][j] - newm);
                sacc[i][j] = p;
                rs += p;
            }
            #pragma unroll
            for (int off = 8; off >= 1; off >>= 1)
                rs += __shfl_xor_sync(0xffffffffu, rs, off);
            const float scale = __expf(mrow[i] - newm);
            lrow[i] = lrow[i] * scale + rs;
            mrow[i] = newm;
            #pragma unroll
            for (int j = 0; j < 4; ++j) oacc[i][j] *= scale;
        }

        #pragma unroll
        for (int i = 0; i < 4; ++i)
            #pragma unroll
            for (int j = 0; j < 4; ++j)
                Ps[(r0 + i) * 65 + (c0 + j)] = sacc[i][j];
        __syncthreads();

        // O += P @ V
        #pragma unroll 8
        for (int j = 0; j < 64; ++j) {
            float pv[4], vv[4];
            #pragma unroll
            for (int i = 0; i < 4; ++i) pv[i] = Ps[(r0 + i) * 65 + j];
            #pragma unroll
            for (int jj = 0; jj < 4; ++jj) vv[jj] = Vs[j * 65 + c0 + jj];
            #pragma unroll
            for (int i = 0; i < 4; ++i)
                #pragma unroll
                for (int jj = 0; jj < 4; ++jj)
                    oacc[i][jj] = fmaf(pv[i], vv[jj], oacc[i][jj]);
        }
    }

    #pragma unroll
    for (int i = 0; i < 4; ++i) {
        const float inv = 1.f / lrow[i];
        const size_t base = ((size_t)b * TT + qt * 64 + r0 + i) * EE + h * 64 + c0;
        #pragma unroll
        for (int jj = 0; jj < 4; ++jj)
            Og[base + jj] = oacc[i][jj] * inv;
    }
}

// ---------------------------------------------------------------------------
extern "C" void kernel_launch(void* const* d_in, const int* in_sizes, int n_in,
                              void* d_out, int out_size)
{
    const float* x     = (const float*)d_in[0];
    const float* y     = (const float*)d_in[1];
    const float* Wqkv1 = (const float*)d_in[2];
    const float* Wqkv2 = (const float*)d_in[3];
    const float* Wout1 = (const float*)d_in[4];
    const float* Wout2 = (const float*)d_in[5];
    float* out = (float*)d_out;

    float *s1, *s2, *xo, *yo;
    cudaGetSymbolAddress((void**)&s1, g_s1);
    cudaGetSymbolAddress((void**)&s2, g_s2);
    cudaGetSymbolAddress((void**)&xo, g_xo);
    cudaGetSymbolAddress((void**)&yo, g_yo);

    // QKV projections with fused split into [3][B][H][T][D]
    gemm_abT_kernel<true><<<dim3(E3 / 128, MTOK / 128), 256>>>(x, Wqkv1, s1, MTOK, E3, EE);
    gemm_abT_kernel<true><<<dim3(E3 / 128, MTOK / 128), 256>>>(y, Wqkv2, s2, MTOK, E3, EE);

    // Cross attention (both streams in one grid)
    const size_t smem = 4 * 64 * 65 * sizeof(float);  // 66560 B
    cudaFuncSetAttribute(cross_attn_kernel,
                         cudaFuncAttributeMaxDynamicSharedMemorySize, (int)smem);
    cross_attn_kernel<<<dim3(TT / 64, BB * HH, 2), 256, smem>>>(s1, s2, xo, yo);

    // Output projections
    gemm_abT_kernel<false><<<dim3(EE / 128, MTOK / 128), 256>>>(xo, Wout1, out, MTOK, EE, EE);
    gemm_abT_kernel<false><<<dim3(EE / 128, MTOK / 128), 256>>>(yo, Wout2, out + (size_t)MTOK * EE, MTOK, EE, EE);
}

// round 7
// speedup vs baseline: 1.6381x; 1.6381x over previous
#include <cuda_runtime.h>
#include <cstdint>
#include <math.h>

#define BBATCH 4
#define TT 1024
#define EE 1024
#define HH 16
#define DDIM 64
#define E3 3072
#define MTOK (BBATCH*TT)   // 4096

// Scratch: qkv split as [3][B][H][T][D], attention outputs as (B,T,E).
__device__ float g_s1[3ull * BBATCH * HH * TT * DDIM];
__device__ float g_s2[3ull * BBATCH * HH * TT * DDIM];
__device__ float g_xo[(size_t)MTOK * EE];
__device__ float g_yo[(size_t)MTOK * EE];

// ---------------------------------------------------------------------------
// helpers (all sm_80-level PTX: valid on plain compute_103 target)
// ---------------------------------------------------------------------------
__device__ __forceinline__ uint32_t smem_u32(const void* p) {
    uint32_t a;
    asm("{ .reg .u64 t; cvta.to.shared.u64 t, %1; cvt.u32.u64 %0, t; }" : "=r"(a) : "l"(p));
    return a;
}
__device__ __forceinline__ uint32_t f2tf(float x) {
    uint32_t r;
    asm("cvt.rna.tf32.f32 %0, %1;" : "=r"(r) : "f"(x));
    return r;
}
__device__ __forceinline__ void cp16(uint32_t dst, const void* src) {
    asm volatile("cp.async.cg.shared.global [%0], [%1], 16;" :: "r"(dst), "l"(src));
}
__device__ __forceinline__ void cp_commit() {
    asm volatile("cp.async.commit_group;" ::: "memory");
}
template<int N>
__device__ __forceinline__ void cp_wait() {
    asm volatile("cp.async.wait_group %0;" :: "n"(N) : "memory");
}
__device__ __forceinline__ void mma_tf32(float* d, const uint32_t* a, const uint32_t* b) {
    asm volatile(
        "mma.sync.aligned.m16n8k8.row.col.f32.tf32.tf32.f32 "
        "{%0,%1,%2,%3}, {%4,%5,%6,%7}, {%8,%9}, {%0,%1,%2,%3};"
        : "+f"(d[0]), "+f"(d[1]), "+f"(d[2]), "+f"(d[3])
        : "r"(a[0]), "r"(a[1]), "r"(a[2]), "r"(a[3]), "r"(b[0]), "r"(b[1]));
}

// ---------------------------------------------------------------------------
// mma.sync tf32 GEMM:  C(M,N) = A(M,K) @ B^T,  B stored (N,K) row-major.
// 128x128x32 CTA tile, 8 warps (2x4), 3-stage cp.async pipeline.
// SPLIT: scatter into [kk][b][h][t][dd] layout (same as R3-passing kernel).
// ---------------------------------------------------------------------------
#define BM 128
#define BN 128
#define BK 32
#define PK 36                       // padded pitch in floats (conflict-free frags)
#define STAGES 3
#define NKT (EE / BK)               // 32
#define STAGE_F ((BM + BN) * PK)    // floats per stage (A+B)
#define SMEM_F (STAGES * STAGE_F)   // 27648 floats = 110592 B

template<bool SPLIT>
__global__ void __launch_bounds__(256, 2) gemm_mma_kernel(
    const float* __restrict__ A, const float* __restrict__ Bm,
    float* __restrict__ C, int N)
{
    extern __shared__ float sm[];
    const int tid = threadIdx.x;
    const int lid = tid & 31;
    const int wid = tid >> 5;
    const int warp_m = wid & 1;        // 2 warps along M
    const int warp_n = wid >> 1;       // 4 warps along N
    const int g = lid >> 2;            // 0..7
    const int q = lid & 3;             // 0..3
    const int row0 = blockIdx.y * BM;
    const int col0 = blockIdx.x * BN;

    const uint32_t sbase = smem_u32(sm);

    // cp.async issue for one stage: A tile rows [row0,row0+128), B rows [col0,col0+128)
    // Each thread: 4 chunks of A + 4 chunks of B (16B each).
    auto issue = [&](int stg, int kt) {
        const uint32_t s_a = sbase + (uint32_t)(stg * STAGE_F) * 4u;
        const uint32_t s_b = s_a + (uint32_t)(BM * PK) * 4u;
        #pragma unroll
        for (int i = 0; i < 4; ++i) {
            const int idx = tid + 256 * i;     // 0..1023
            const int r = idx >> 3;            // row 0..127
            const int c = (idx & 7) * 4;       // col 0,4,..,28
            cp16(s_a + (uint32_t)(r * PK + c) * 4u,
                 A + (size_t)(row0 + r) * EE + kt * BK + c);
            cp16(s_b + (uint32_t)(r * PK + c) * 4u,
                 Bm + (size_t)(col0 + r) * EE + kt * BK + c);
        }
    };

    float acc[4][4][4];
    #pragma unroll
    for (int i = 0; i < 4; ++i)
        #pragma unroll
        for (int j = 0; j < 4; ++j)
            #pragma unroll
            for (int r = 0; r < 4; ++r) acc[i][j][r] = 0.f;

    // prologue: stages 0 .. STAGES-2
    #pragma unroll
    for (int s = 0; s < STAGES - 1; ++s) { issue(s, s); cp_commit(); }

    for (int kt = 0; kt < NKT; ++kt) {
        // stages <= kt must be complete. Newest in-flight stage is
        // min(kt+1, NKT-1): allow 1 pending unless it IS stage kt.
        if (kt < NKT - 1) cp_wait<1>(); else cp_wait<0>();
        __syncthreads();   // whole tile visible; also: all warps done reading
                           // the stage we are about to overwrite (program order)

        if (kt + STAGES - 1 < NKT) {
            issue((kt + STAGES - 1) % STAGES, kt + STAGES - 1);
            cp_commit();
        }

        const float* as = sm + (kt % STAGES) * STAGE_F;
        const float* bs = as + BM * PK;

        #pragma unroll
        for (int ks = 0; ks < 4; ++ks) {
            const int k0 = ks * 8;
            uint32_t af[4][4], bf[4][2];
            #pragma unroll
            for (int im = 0; im < 4; ++im) {
                const int mr = warp_m * 64 + im * 16 + g;
                af[im][0] = f2tf(as[mr * PK + k0 + q]);
                af[im][1] = f2tf(as[(mr + 8) * PK + k0 + q]);
                af[im][2] = f2tf(as[mr * PK + k0 + q + 4]);
                af[im][3] = f2tf(as[(mr + 8) * PK + k0 + q + 4]);
            }
            #pragma unroll
            for (int jn = 0; jn < 4; ++jn) {
                const int nc = warp_n * 32 + jn * 8 + g;
                bf[jn][0] = f2tf(bs[nc * PK + k0 + q]);
                bf[jn][1] = f2tf(bs[nc * PK + k0 + q + 4]);
            }
            #pragma unroll
            for (int im = 0; im < 4; ++im)
                #pragma unroll
                for (int jn = 0; jn < 4; ++jn)
                    mma_tf32(acc[im][jn], af[im], bf[jn]);
        }
    }

    // epilogue
    #pragma unroll
    for (int im = 0; im < 4; ++im) {
        #pragma unroll
        for (int jn = 0; jn < 4; ++jn) {
            const int mrow = row0 + warp_m * 64 + im * 16 + g;
            const int ncol = col0 + warp_n * 32 + jn * 8 + 2 * q;
            #pragma unroll
            for (int rg = 0; rg < 4; ++rg) {
                const int m = mrow + ((rg >> 1) << 3);
                const int n = ncol + (rg & 1);
                if (SPLIT) {
                    // n = dd*48 + kk*16 + hh ; m = bb*T + t
                    const int dd = n / 48;
                    const int rr = n - dd * 48;
                    const int kk = rr >> 4;
                    const int hh = rr & 15;
                    const int bb = m >> 10;
                    const int t  = m & 1023;
                    C[((((size_t)kk * BBATCH + bb) * HH + hh) * TT + t) * DDIM + dd] =
                        acc[im][jn][rg];
                } else {
                    C[(size_t)m * N + n] = acc[im][jn][rg];
                }
            }
        }
    }
}

// ---------------------------------------------------------------------------
// Dual-stream cross attention, fp32 flash style (R3-passing version).
// s1/s2: [3][B][H][T][D].  z=0: Q from s2, K/V from s1 -> xo.  Output (B,T,E).
// ---------------------------------------------------------------------------
__global__ void __launch_bounds__(256) cross_attn_kernel(
    const float* __restrict__ s1, const float* __restrict__ s2,
    float* __restrict__ xo, float* __restrict__ yo)
{
    extern __shared__ float sma[];
    float* Qs = sma;                 // [64][65]
    float* Ks = sma + 64 * 65;
    float* Vs = sma + 2 * 64 * 65;
    float* Ps = sma + 3 * 64 * 65;

    const int tid = threadIdx.x;
    const int tx  = tid & 15;
    const int ty  = tid >> 4;
    const int qt  = blockIdx.x;          // 0..15
    const int b   = blockIdx.y >> 4;
    const int h   = blockIdx.y & 15;
    const int st  = blockIdx.z;          // 0: xo, 1: yo

    const float* Qg = (st == 0) ? s2 : s1;
    const float* Kg = (st == 0) ? s1 : s2;
    float*       Og = (st == 0) ? xo : yo;

    const size_t plane  = (size_t)BBATCH * HH * TT * DDIM;
    const size_t bhBase = ((size_t)b * HH + h) * TT * DDIM;
    const float* Qbase = Qg + bhBase + (size_t)qt * 64 * DDIM;   // kk=0
    const float* Kbase = Kg + plane     + bhBase;                // kk=1
    const float* Vbase = Kg + 2 * plane + bhBase;                // kk=2

    for (int i = tid; i < 64 * 64; i += 256) {
        const int r = i >> 6, c = i & 63;
        Qs[r * 65 + c] = Qbase[i];
    }

    float oacc[4][4];
    #pragma unroll
    for (int i = 0; i < 4; ++i)
        #pragma unroll
        for (int j = 0; j < 4; ++j) oacc[i][j] = 0.f;
    float mrow[4], lrow[4];
    #pragma unroll
    for (int i = 0; i < 4; ++i) { mrow[i] = -1e30f; lrow[i] = 0.f; }

    const int r0 = ty * 4;
    const int c0 = tx * 4;

    for (int kt = 0; kt < TT / 64; ++kt) {
        __syncthreads();
        const float* kb = Kbase + (size_t)kt * 64 * DDIM;
        const float* vb = Vbase + (size_t)kt * 64 * DDIM;
        for (int i = tid; i < 64 * 64; i += 256) {
            const int r = i >> 6, c = i & 63;
            Ks[r * 65 + c] = kb[i];
            Vs[r * 65 + c] = vb[i];
        }
        __syncthreads();

        float sacc[4][4];
        #pragma unroll
        for (int i = 0; i < 4; ++i)
            #pragma unroll
            for (int j = 0; j < 4; ++j) sacc[i][j] = 0.f;

        #pragma unroll 8
        for (int k = 0; k < 64; ++k) {
            float qv[4], kv[4];
            #pragma unroll
            for (int i = 0; i < 4; ++i) qv[i] = Qs[(r0 + i) * 65 + k];
            #pragma unroll
            for (int j = 0; j < 4; ++j) kv[j] = Ks[(c0 + j) * 65 + k];
            #pragma unroll
            for (int i = 0; i < 4; ++i)
                #pragma unroll
                for (int j = 0; j < 4; ++j)
                    sacc[i][j] = fmaf(qv[i], kv[j], sacc[i][j]);
        }

        #pragma unroll
        for (int i = 0; i < 4; ++i) {
            float tm = -1e30f;
            #pragma unroll
            for (int j = 0; j < 4; ++j) {
                sacc[i][j] *= 0.125f;
                tm = fmaxf(tm, sacc[i][j]);
            }
            #pragma unroll
            for (int off = 8; off >= 1; off >>= 1)
                tm = fmaxf(tm, __shfl_xor_sync(0xffffffffu, tm, off));
            const float newm = fmaxf(mrow[i], tm);
            float rs = 0.f;
            #pragma unroll
            for (int j = 0; j < 4; ++j) {
                const float p = __expf(sacc[i][j] - newm);
                sacc[i][j] = p;
                rs += p;
            }
            #pragma unroll
            for (int off = 8; off >= 1; off >>= 1)
                rs += __shfl_xor_sync(0xffffffffu, rs, off);
            const float scale = __expf(mrow[i] - newm);
            lrow[i] = lrow[i] * scale + rs;
            mrow[i] = newm;
            #pragma unroll
            for (int j = 0; j < 4; ++j) oacc[i][j] *= scale;
        }

        #pragma unroll
        for (int i = 0; i < 4; ++i)
            #pragma unroll
            for (int j = 0; j < 4; ++j)
                Ps[(r0 + i) * 65 + (c0 + j)] = sacc[i][j];
        __syncthreads();

        #pragma unroll 8
        for (int j = 0; j < 64; ++j) {
            float pv[4], vv[4];
            #pragma unroll
            for (int i = 0; i < 4; ++i) pv[i] = Ps[(r0 + i) * 65 + j];
            #pragma unroll
            for (int jj = 0; jj < 4; ++jj) vv[jj] = Vs[j * 65 + c0 + jj];
            #pragma unroll
            for (int i = 0; i < 4; ++i)
                #pragma unroll
                for (int jj = 0; jj < 4; ++jj)
                    oacc[i][jj] = fmaf(pv[i], vv[jj], oacc[i][jj]);
        }
    }

    #pragma unroll
    for (int i = 0; i < 4; ++i) {
        const float inv = 1.f / lrow[i];
        const size_t base = ((size_t)b * TT + qt * 64 + r0 + i) * EE + h * 64 + c0;
        #pragma unroll
        for (int jj = 0; jj < 4; ++jj)
            Og[base + jj] = oacc[i][jj] * inv;
    }
}

// ---------------------------------------------------------------------------
extern "C" void kernel_launch(void* const* d_in, const int* in_sizes, int n_in,
                              void* d_out, int out_size)
{
    const float* x     = (const float*)d_in[0];
    const float* y     = (const float*)d_in[1];
    const float* Wqkv1 = (const float*)d_in[2];
    const float* Wqkv2 = (const float*)d_in[3];
    const float* Wout1 = (const float*)d_in[4];
    const float* Wout2 = (const float*)d_in[5];
    float* out = (float*)d_out;

    float *s1, *s2, *xo, *yo;
    cudaGetSymbolAddress((void**)&s1, g_s1);
    cudaGetSymbolAddress((void**)&s2, g_s2);
    cudaGetSymbolAddress((void**)&xo, g_xo);
    cudaGetSymbolAddress((void**)&yo, g_yo);

    const int gsmem = SMEM_F * sizeof(float);   // 110592
    cudaFuncSetAttribute(gemm_mma_kernel<true>,
                         cudaFuncAttributeMaxDynamicSharedMemorySize, gsmem);
    cudaFuncSetAttribute(gemm_mma_kernel<false>,
                         cudaFuncAttributeMaxDynamicSharedMemorySize, gsmem);

    // QKV projections (tf32 mma.sync) with fused split into [3][B][H][T][D]
    gemm_mma_kernel<true><<<dim3(E3 / BN, MTOK / BM), 256, gsmem>>>(x, Wqkv1, s1, E3);
    gemm_mma_kernel<true><<<dim3(E3 / BN, MTOK / BM), 256, gsmem>>>(y, Wqkv2, s2, E3);

    // Cross attention (fp32)
    const size_t asmem = 4 * 64 * 65 * sizeof(float);
    cudaFuncSetAttribute(cross_attn_kernel,
                         cudaFuncAttributeMaxDynamicSharedMemorySize, (int)asmem);
    cross_attn_kernel<<<dim3(TT / 64, BBATCH * HH, 2), 256, asmem>>>(s1, s2, xo, yo);

    // Output projections (tf32 mma.sync)
    gemm_mma_kernel<false><<<dim3(EE / BN, MTOK / BM), 256, gsmem>>>(xo, Wout1, out, EE);
    gemm_mma_kernel<false><<<dim3(EE / BN, MTOK / BM), 256, gsmem>>>(yo, Wout2, out + (size_t)MTOK * EE, EE);
}

// round 9
// speedup vs baseline: 2.6365x; 1.6095x over previous
#include <cuda_runtime.h>
#include <cstdint>
#include <math.h>

#define BBATCH 4
#define TT 1024
#define EE 1024
#define HH 16
#define DDIM 64
#define E3 3072
#define MTOK (BBATCH*TT)   // 4096

// Scratch: qkv split as [3][B][H][T][D], attention outputs as (B,T,E).
__device__ float g_s1[3ull * BBATCH * HH * TT * DDIM];
__device__ float g_s2[3ull * BBATCH * HH * TT * DDIM];
__device__ float g_xo[(size_t)MTOK * EE];
__device__ float g_yo[(size_t)MTOK * EE];

// ---------------------------------------------------------------------------
// helpers (all sm_80-level PTX: valid on plain compute_103 target)
// ---------------------------------------------------------------------------
__device__ __forceinline__ uint32_t smem_u32(const void* p) {
    uint32_t a;
    asm("{ .reg .u64 t; cvta.to.shared.u64 t, %1; cvt.u32.u64 %0, t; }" : "=r"(a) : "l"(p));
    return a;
}
__device__ __forceinline__ uint32_t f2tf(float x) {
    uint32_t r;
    asm("cvt.rna.tf32.f32 %0, %1;" : "=r"(r) : "f"(x));
    return r;
}
__device__ __forceinline__ void cp16(uint32_t dst, const void* src) {
    asm volatile("cp.async.cg.shared.global [%0], [%1], 16;" :: "r"(dst), "l"(src));
}
__device__ __forceinline__ void cp_commit() {
    asm volatile("cp.async.commit_group;" ::: "memory");
}
template<int N>
__device__ __forceinline__ void cp_wait() {
    asm volatile("cp.async.wait_group %0;" :: "n"(N) : "memory");
}
__device__ __forceinline__ void mma_tf32(float* d, const uint32_t* a, const uint32_t* b) {
    asm volatile(
        "mma.sync.aligned.m16n8k8.row.col.f32.tf32.tf32.f32 "
        "{%0,%1,%2,%3}, {%4,%5,%6,%7}, {%8,%9}, {%0,%1,%2,%3};"
        : "+f"(d[0]), "+f"(d[1]), "+f"(d[2]), "+f"(d[3])
        : "r"(a[0]), "r"(a[1]), "r"(a[2]), "r"(a[3]), "r"(b[0]), "r"(b[1]));
}

// ---------------------------------------------------------------------------
// mma.sync tf32 GEMM:  C(M,N) = A(M,K) @ B^T,  B stored (N,K) row-major.
// 128x128x32 CTA tile, 8 warps (2x4), 3-stage cp.async pipeline. (R7, passing)
// ---------------------------------------------------------------------------
#define BM 128
#define BN 128
#define BK 32
#define PK 36
#define STAGES 3
#define NKT (EE / BK)
#define STAGE_F ((BM + BN) * PK)
#define SMEM_F (STAGES * STAGE_F)

template<bool SPLIT>
__global__ void __launch_bounds__(256, 2) gemm_mma_kernel(
    const float* __restrict__ A, const float* __restrict__ Bm,
    float* __restrict__ C, int N)
{
    extern __shared__ float sm[];
    const int tid = threadIdx.x;
    const int lid = tid & 31;
    const int wid = tid >> 5;
    const int warp_m = wid & 1;
    const int warp_n = wid >> 1;
    const int g = lid >> 2;
    const int q = lid & 3;
    const int row0 = blockIdx.y * BM;
    const int col0 = blockIdx.x * BN;

    const uint32_t sbase = smem_u32(sm);

    auto issue = [&](int stg, int kt) {
        const uint32_t s_a = sbase + (uint32_t)(stg * STAGE_F) * 4u;
        const uint32_t s_b = s_a + (uint32_t)(BM * PK) * 4u;
        #pragma unroll
        for (int i = 0; i < 4; ++i) {
            const int idx = tid + 256 * i;
            const int r = idx >> 3;
            const int c = (idx & 7) * 4;
            cp16(s_a + (uint32_t)(r * PK + c) * 4u,
                 A + (size_t)(row0 + r) * EE + kt * BK + c);
            cp16(s_b + (uint32_t)(r * PK + c) * 4u,
                 Bm + (size_t)(col0 + r) * EE + kt * BK + c);
        }
    };

    float acc[4][4][4];
    #pragma unroll
    for (int i = 0; i < 4; ++i)
        #pragma unroll
        for (int j = 0; j < 4; ++j)
            #pragma unroll
            for (int r = 0; r < 4; ++r) acc[i][j][r] = 0.f;

    #pragma unroll
    for (int s = 0; s < STAGES - 1; ++s) { issue(s, s); cp_commit(); }

    for (int kt = 0; kt < NKT; ++kt) {
        if (kt < NKT - 1) cp_wait<1>(); else cp_wait<0>();
        __syncthreads();

        if (kt + STAGES - 1 < NKT) {
            issue((kt + STAGES - 1) % STAGES, kt + STAGES - 1);
            cp_commit();
        }

        const float* as = sm + (kt % STAGES) * STAGE_F;
        const float* bs = as + BM * PK;

        #pragma unroll
        for (int ks = 0; ks < 4; ++ks) {
            const int k0 = ks * 8;
            uint32_t af[4][4], bf[4][2];
            #pragma unroll
            for (int im = 0; im < 4; ++im) {
                const int mr = warp_m * 64 + im * 16 + g;
                af[im][0] = f2tf(as[mr * PK + k0 + q]);
                af[im][1] = f2tf(as[(mr + 8) * PK + k0 + q]);
                af[im][2] = f2tf(as[mr * PK + k0 + q + 4]);
                af[im][3] = f2tf(as[(mr + 8) * PK + k0 + q + 4]);
            }
            #pragma unroll
            for (int jn = 0; jn < 4; ++jn) {
                const int nc = warp_n * 32 + jn * 8 + g;
                bf[jn][0] = f2tf(bs[nc * PK + k0 + q]);
                bf[jn][1] = f2tf(bs[nc * PK + k0 + q + 4]);
            }
            #pragma unroll
            for (int im = 0; im < 4; ++im)
                #pragma unroll
                for (int jn = 0; jn < 4; ++jn)
                    mma_tf32(acc[im][jn], af[im], bf[jn]);
        }
    }

    #pragma unroll
    for (int im = 0; im < 4; ++im) {
        #pragma unroll
        for (int jn = 0; jn < 4; ++jn) {
            const int mrow = row0 + warp_m * 64 + im * 16 + g;
            const int ncol = col0 + warp_n * 32 + jn * 8 + 2 * q;
            #pragma unroll
            for (int rg = 0; rg < 4; ++rg) {
                const int m = mrow + ((rg >> 1) << 3);
                const int n = ncol + (rg & 1);
                if (SPLIT) {
                    const int dd = n / 48;
                    const int rr = n - dd * 48;
                    const int kk = rr >> 4;
                    const int hh = rr & 15;
                    const int bb = m >> 10;
                    const int t  = m & 1023;
                    C[((((size_t)kk * BBATCH + bb) * HH + hh) * TT + t) * DDIM + dd] =
                        acc[im][jn][rg];
                } else {
                    C[(size_t)m * N + n] = acc[im][jn][rg];
                }
            }
        }
    }
}

// ---------------------------------------------------------------------------
// Dual-stream cross attention with mma.sync tf32 fragments.
// s1/s2: [3][B][H][T][D].  z=0: Q from s2, K/V from s1 -> xo.  Output (B,T,E).
// Q tile 128, KV tile 64. 8 warps, each owns 16 q-rows.
// All tiles stored in smem as tf32 (uint32), pitch 68 (== 4 mod 32 ->
// fragment LDS addresses hit bank lid: conflict-free, same as GEMM kernel).
// ---------------------------------------------------------------------------
#define TQ 128
#define TK 64
#define AP 68
#define AQ0 0
#define AK0 (TQ * AP)                 // 8704
#define AV0 (AK0 + TK * AP)           // 13056
#define AP0 (AV0 + TK * AP)           // 17408
#define ASMEM_U (AP0 + 8 * 16 * AP)   // 26112 u32 = 104448 B

__global__ void __launch_bounds__(256, 2) attn_tc_kernel(
    const float* __restrict__ s1, const float* __restrict__ s2,
    float* __restrict__ xo, float* __restrict__ yo)
{
    extern __shared__ uint32_t smu[];
    const int tid = threadIdx.x;
    const int lid = tid & 31;
    const int w   = tid >> 5;
    const int g   = lid >> 2;          // 0..7
    const int q   = lid & 3;           // 0..3
    const int qt  = blockIdx.x;        // 0..7
    const int b   = blockIdx.y >> 4;
    const int h   = blockIdx.y & 15;
    const int st  = blockIdx.z;

    const float* Qg = (st == 0) ? s2 : s1;
    const float* Kg = (st == 0) ? s1 : s2;
    float*       Og = (st == 0) ? xo : yo;

    const size_t plane = (size_t)BBATCH * HH * TT * DDIM;
    const size_t bh    = ((size_t)b * HH + h) * TT * DDIM;
    const float* Qb = Qg + bh + (size_t)qt * TQ * DDIM;   // kk=0
    const float* Kb = Kg + plane + bh;                    // kk=1
    const float* Vb = Kg + 2 * plane + bh;                // kk=2

    // load Q tile (128x64) as tf32, K-major, pitch AP
    for (int i = tid; i < TQ * DDIM; i += 256)
        smu[AQ0 + (i >> 6) * AP + (i & 63)] = f2tf(Qb[i]);

    float oacc[8][4];
    #pragma unroll
    for (int nt = 0; nt < 8; ++nt)
        #pragma unroll
        for (int r = 0; r < 4; ++r) oacc[nt][r] = 0.f;
    float mrow[2] = {-1e30f, -1e30f};
    float lrow[2] = {0.f, 0.f};

    uint32_t* Pw = smu + AP0 + w * 16 * AP;   // warp-private P staging
    const int mr = w * 16;

    for (int kt = 0; kt < TT / TK; ++kt) {
        __syncthreads();   // WAR: K/V tiles from previous iteration fully read
        const float* kb = Kb + (size_t)kt * TK * DDIM;
        const float* vb = Vb + (size_t)kt * TK * DDIM;
        for (int i = tid; i < TK * DDIM; i += 256) {
            const int t = i >> 6, d = i & 63;
            smu[AK0 + t * AP + d] = f2tf(kb[i]);
            smu[AV0 + d * AP + t] = f2tf(vb[i]);   // V transposed: d-major
        }
        __syncthreads();

        // S = Q @ K^T  (warp rows mr..mr+15, all 64 kv cols)
        float sacc[8][4];
        #pragma unroll
        for (int nt = 0; nt < 8; ++nt)
            #pragma unroll
            for (int r = 0; r < 4; ++r) sacc[nt][r] = 0.f;

        #pragma unroll
        for (int ks = 0; ks < 8; ++ks) {
            const int k0 = ks * 8;
            uint32_t af[4];
            af[0] = smu[AQ0 + (mr + g) * AP + k0 + q];
            af[1] = smu[AQ0 + (mr + g + 8) * AP + k0 + q];
            af[2] = smu[AQ0 + (mr + g) * AP + k0 + q + 4];
            af[3] = smu[AQ0 + (mr + g + 8) * AP + k0 + q + 4];
            #pragma unroll
            for (int nt = 0; nt < 8; ++nt) {
                uint32_t bf[2];
                bf[0] = smu[AK0 + (nt * 8 + g) * AP + k0 + q];
                bf[1] = smu[AK0 + (nt * 8 + g) * AP + k0 + q + 4];
                mma_tf32(sacc[nt], af, bf);
            }
        }

        // online softmax: i=0 -> row g, i=1 -> row g+8 (C frag: c[2i],c[2i+1])
        #pragma unroll
        for (int i = 0; i < 2; ++i) {
            float tm = -1e30f;
            #pragma unroll
            for (int nt = 0; nt < 8; ++nt) {
                sacc[nt][2*i]   *= 0.125f;
                sacc[nt][2*i+1] *= 0.125f;
                tm = fmaxf(tm, fmaxf(sacc[nt][2*i], sacc[nt][2*i+1]));
            }
            tm = fmaxf(tm, __shfl_xor_sync(0xffffffffu, tm, 1));
            tm = fmaxf(tm, __shfl_xor_sync(0xffffffffu, tm, 2));
            const float newm = fmaxf(mrow[i], tm);
            float rs = 0.f;
            #pragma unroll
            for (int nt = 0; nt < 8; ++nt) {
                const float p0 = __expf(sacc[nt][2*i]   - newm);
                const float p1 = __expf(sacc[nt][2*i+1] - newm);
                sacc[nt][2*i] = p0; sacc[nt][2*i+1] = p1;
                rs += p0 + p1;
            }
            rs += __shfl_xor_sync(0xffffffffu, rs, 1);
            rs += __shfl_xor_sync(0xffffffffu, rs, 2);
            const float sc = __expf(mrow[i] - newm);
            lrow[i] = lrow[i] * sc + rs;
            mrow[i] = newm;
            #pragma unroll
            for (int nt = 0; nt < 8; ++nt) {
                oacc[nt][2*i]   *= sc;
                oacc[nt][2*i+1] *= sc;
            }
        }

        // stage P as tf32 (C layout -> smem), then read back as A fragments
        #pragma unroll
        for (int nt = 0; nt < 8; ++nt) {
            Pw[g * AP + nt * 8 + 2*q]           = f2tf(sacc[nt][0]);
            Pw[g * AP + nt * 8 + 2*q + 1]       = f2tf(sacc[nt][1]);
            Pw[(g + 8) * AP + nt * 8 + 2*q]     = f2tf(sacc[nt][2]);
            Pw[(g + 8) * AP + nt * 8 + 2*q + 1] = f2tf(sacc[nt][3]);
        }
        __syncwarp();

        // O += P @ V   (B = Vs[d][t]: row.col gives sum_t P[r,t] V[t,d])
        #pragma unroll
        for (int ks = 0; ks < 8; ++ks) {
            const int k0 = ks * 8;
            uint32_t pa[4];
            pa[0] = Pw[g * AP + k0 + q];
            pa[1] = Pw[(g + 8) * AP + k0 + q];
            pa[2] = Pw[g * AP + k0 + q + 4];
            pa[3] = Pw[(g + 8) * AP + k0 + q + 4];
            #pragma unroll
            for (int nt = 0; nt < 8; ++nt) {
                uint32_t vf[2];
                vf[0] = smu[AV0 + (nt * 8 + g) * AP + k0 + q];
                vf[1] = smu[AV0 + (nt * 8 + g) * AP + k0 + q + 4];
                mma_tf32(oacc[nt], pa, vf);
            }
        }
    }

    // write O: row m, cols h*64 + nt*8 + 2q (+1)  -- float2 stores
    #pragma unroll
    for (int i = 0; i < 2; ++i) {
        const float inv = 1.f / lrow[i];
        const int m = qt * TQ + mr + g + 8 * i;
        float* orow = Og + ((size_t)b * TT + m) * EE + h * 64;
        #pragma unroll
        for (int nt = 0; nt < 8; ++nt) {
            float2 v;
            v.x = oacc[nt][2*i]   * inv;
            v.y = oacc[nt][2*i+1] * inv;
            *(float2*)(orow + nt * 8 + 2 * q) = v;
        }
    }
}

// ---------------------------------------------------------------------------
extern "C" void kernel_launch(void* const* d_in, const int* in_sizes, int n_in,
                              void* d_out, int out_size)
{
    const float* x     = (const float*)d_in[0];
    const float* y     = (const float*)d_in[1];
    const float* Wqkv1 = (const float*)d_in[2];
    const float* Wqkv2 = (const float*)d_in[3];
    const float* Wout1 = (const float*)d_in[4];
    const float* Wout2 = (const float*)d_in[5];
    float* out = (float*)d_out;

    float *s1, *s2, *xo, *yo;
    cudaGetSymbolAddress((void**)&s1, g_s1);
    cudaGetSymbolAddress((void**)&s2, g_s2);
    cudaGetSymbolAddress((void**)&xo, g_xo);
    cudaGetSymbolAddress((void**)&yo, g_yo);

    const int gsmem = SMEM_F * sizeof(float);   // 110592
    cudaFuncSetAttribute(gemm_mma_kernel<true>,
                         cudaFuncAttributeMaxDynamicSharedMemorySize, gsmem);
    cudaFuncSetAttribute(gemm_mma_kernel<false>,
                         cudaFuncAttributeMaxDynamicSharedMemorySize, gsmem);

    // QKV projections (tf32 mma.sync) with fused split into [3][B][H][T][D]
    gemm_mma_kernel<true><<<dim3(E3 / BN, MTOK / BM), 256, gsmem>>>(x, Wqkv1, s1, E3);
    gemm_mma_kernel<true><<<dim3(E3 / BN, MTOK / BM), 256, gsmem>>>(y, Wqkv2, s2, E3);

    // Cross attention (tf32 mma.sync flash)
    const int asmem = ASMEM_U * sizeof(uint32_t);   // 104448
    cudaFuncSetAttribute(attn_tc_kernel,
                         cudaFuncAttributeMaxDynamicSharedMemorySize, asmem);
    attn_tc_kernel<<<dim3(TT / TQ, BBATCH * HH, 2), 256, asmem>>>(s1, s2, xo, yo);

    // Output projections (tf32 mma.sync)
    gemm_mma_kernel<false><<<dim3(EE / BN, MTOK / BM), 256, gsmem>>>(xo, Wout1, out, EE);
    gemm_mma_kernel<false><<<dim3(EE / BN, MTOK / BM), 256, gsmem>>>(yo, Wout2, out + (size_t)MTOK * EE, EE);
}

// round 12
// speedup vs baseline: 2.6944x; 1.0219x over previous
#include <cuda_runtime.h>
#include <cstdint>
#include <math.h>

#define BBATCH 4
#define TT 1024
#define EE 1024
#define HH 16
#define DDIM 64
#define E3 3072
#define MTOK (BBATCH*TT)   // 4096

// Scratch: qkv split as [3][B][H][T][D], attention outputs as (B,T,E),
// plus tf32-pre-rounded copies of all six inputs.
__device__ float g_s1[3ull * BBATCH * HH * TT * DDIM];
__device__ float g_s2[3ull * BBATCH * HH * TT * DDIM];
__device__ float g_xo[(size_t)MTOK * EE];
__device__ float g_yo[(size_t)MTOK * EE];
__device__ float g_rx[(size_t)MTOK * EE];
__device__ float g_ry[(size_t)MTOK * EE];
__device__ float g_rwq1[(size_t)E3 * EE];
__device__ float g_rwq2[(size_t)E3 * EE];
__device__ float g_rwo1[(size_t)EE * EE];
__device__ float g_rwo2[(size_t)EE * EE];

// ---------------------------------------------------------------------------
// helpers (all sm_80-level PTX: valid on plain compute_103 target)
// ---------------------------------------------------------------------------
__device__ __forceinline__ uint32_t smem_u32(const void* p) {
    uint32_t a;
    asm("{ .reg .u64 t; cvta.to.shared.u64 t, %1; cvt.u32.u64 %0, t; }" : "=r"(a) : "l"(p));
    return a;
}
__device__ __forceinline__ uint32_t f2tf(float x) {
    uint32_t r;
    asm("cvt.rna.tf32.f32 %0, %1;" : "=r"(r) : "f"(x));
    return r;
}
__device__ __forceinline__ void cp16(uint32_t dst, const void* src) {
    asm volatile("cp.async.cg.shared.global [%0], [%1], 16;" :: "r"(dst), "l"(src));
}
__device__ __forceinline__ void cp_commit() {
    asm volatile("cp.async.commit_group;" ::: "memory");
}
template<int N>
__device__ __forceinline__ void cp_wait() {
    asm volatile("cp.async.wait_group %0;" :: "n"(N) : "memory");
}
__device__ __forceinline__ void mma_tf32(float* d, const uint32_t* a, const uint32_t* b) {
    asm volatile(
        "mma.sync.aligned.m16n8k8.row.col.f32.tf32.tf32.f32 "
        "{%0,%1,%2,%3}, {%4,%5,%6,%7}, {%8,%9}, {%0,%1,%2,%3};"
        : "+f"(d[0]), "+f"(d[1]), "+f"(d[2]), "+f"(d[3])
        : "r"(a[0]), "r"(a[1]), "r"(a[2]), "r"(a[3]), "r"(b[0]), "r"(b[1]));
}

// ---------------------------------------------------------------------------
// Pre-round: dst = tf32_rna(src), vectorized. One pass, idempotent.
// ---------------------------------------------------------------------------
__global__ void __launch_bounds__(256) round_tf32_kernel(
    const float4* __restrict__ src, float4* __restrict__ dst, int n4)
{
    const int i = blockIdx.x * 256 + threadIdx.x;
    if (i < n4) {
        float4 v = src[i];
        v.x = __uint_as_float(f2tf(v.x));
        v.y = __uint_as_float(f2tf(v.y));
        v.z = __uint_as_float(f2tf(v.z));
        v.w = __uint_as_float(f2tf(v.w));
        dst[i] = v;
    }
}

// ---------------------------------------------------------------------------
// mma.sync tf32 GEMM:  C(M,N) = A(M,K) @ B^T,  B stored (N,K) row-major.
// Inputs MUST be tf32-pre-rounded (fragments loaded with no cvt).
// 128x128x32 CTA tile, 8 warps (2x4), 3-stage cp.async pipeline.
// SPLIT: scatter tf32-ROUNDED values into [kk][b][h][t][dd] layout.
// ---------------------------------------------------------------------------
#define BM 128
#define BN 128
#define BK 32
#define PK 36
#define STAGES 3
#define NKT (EE / BK)
#define STAGE_F ((BM + BN) * PK)
#define SMEM_F (STAGES * STAGE_F)

template<bool SPLIT>
__global__ void __launch_bounds__(256, 2) gemm_mma_kernel(
    const float* __restrict__ A, const float* __restrict__ Bm,
    float* __restrict__ C, int N)
{
    extern __shared__ float sm[];
    const int tid = threadIdx.x;
    const int lid = tid & 31;
    const int wid = tid >> 5;
    const int warp_m = wid & 1;
    const int warp_n = wid >> 1;
    const int g = lid >> 2;
    const int q = lid & 3;
    const int row0 = blockIdx.y * BM;
    const int col0 = blockIdx.x * BN;

    const uint32_t sbase = smem_u32(sm);

    auto issue = [&](int stg, int kt) {
        const uint32_t s_a = sbase + (uint32_t)(stg * STAGE_F) * 4u;
        const uint32_t s_b = s_a + (uint32_t)(BM * PK) * 4u;
        #pragma unroll
        for (int i = 0; i < 4; ++i) {
            const int idx = tid + 256 * i;
            const int r = idx >> 3;
            const int c = (idx & 7) * 4;
            cp16(s_a + (uint32_t)(r * PK + c) * 4u,
                 A + (size_t)(row0 + r) * EE + kt * BK + c);
            cp16(s_b + (uint32_t)(r * PK + c) * 4u,
                 Bm + (size_t)(col0 + r) * EE + kt * BK + c);
        }
    };

    float acc[4][4][4];
    #pragma unroll
    for (int i = 0; i < 4; ++i)
        #pragma unroll
        for (int j = 0; j < 4; ++j)
            #pragma unroll
            for (int r = 0; r < 4; ++r) acc[i][j][r] = 0.f;

    #pragma unroll
    for (int s = 0; s < STAGES - 1; ++s) { issue(s, s); cp_commit(); }

    for (int kt = 0; kt < NKT; ++kt) {
        if (kt < NKT - 1) cp_wait<1>(); else cp_wait<0>();
        __syncthreads();

        if (kt + STAGES - 1 < NKT) {
            issue((kt + STAGES - 1) % STAGES, kt + STAGES - 1);
            cp_commit();
        }

        const float* as = sm + (kt % STAGES) * STAGE_F;
        const float* bs = as + BM * PK;

        #pragma unroll
        for (int ks = 0; ks < 4; ++ks) {
            const int k0 = ks * 8;
            uint32_t af[4][4], bf[4][2];
            #pragma unroll
            for (int im = 0; im < 4; ++im) {
                const int mr = warp_m * 64 + im * 16 + g;
                af[im][0] = __float_as_uint(as[mr * PK + k0 + q]);
                af[im][1] = __float_as_uint(as[(mr + 8) * PK + k0 + q]);
                af[im][2] = __float_as_uint(as[mr * PK + k0 + q + 4]);
                af[im][3] = __float_as_uint(as[(mr + 8) * PK + k0 + q + 4]);
            }
            #pragma unroll
            for (int jn = 0; jn < 4; ++jn) {
                const int nc = warp_n * 32 + jn * 8 + g;
                bf[jn][0] = __float_as_uint(bs[nc * PK + k0 + q]);
                bf[jn][1] = __float_as_uint(bs[nc * PK + k0 + q + 4]);
            }
            #pragma unroll
            for (int im = 0; im < 4; ++im)
                #pragma unroll
                for (int jn = 0; jn < 4; ++jn)
                    mma_tf32(acc[im][jn], af[im], bf[jn]);
        }
    }

    #pragma unroll
    for (int im = 0; im < 4; ++im) {
        #pragma unroll
        for (int jn = 0; jn < 4; ++jn) {
            const int mrow = row0 + warp_m * 64 + im * 16 + g;
            const int ncol = col0 + warp_n * 32 + jn * 8 + 2 * q;
            #pragma unroll
            for (int rg = 0; rg < 4; ++rg) {
                const int m = mrow + ((rg >> 1) << 3);
                const int n = ncol + (rg & 1);
                if (SPLIT) {
                    // write ROUNDED so attention needs no cvt on Q/K/V
                    const int dd = n / 48;
                    const int rr = n - dd * 48;
                    const int kk = rr >> 4;
                    const int hh = rr & 15;
                    const int bb = m >> 10;
                    const int t  = m & 1023;
                    C[((((size_t)kk * BBATCH + bb) * HH + hh) * TT + t) * DDIM + dd] =
                        __uint_as_float(f2tf(acc[im][jn][rg]));
                } else {
                    C[(size_t)m * N + n] = acc[im][jn][rg];
                }
            }
        }
    }
}

// ---------------------------------------------------------------------------
// Dual-stream cross attention with mma.sync tf32 fragments.
// s1/s2: [3][B][H][T][D], values tf32-pre-rounded (no cvt on load).
// z=0: Q from s2, K/V from s1 -> xo.  Output (B,T,E), written rounded.
// Q tile 128, KV tile 64. 8 warps, each owns 16 q-rows. Pitch 68: conflict-free.
// ---------------------------------------------------------------------------
#define TQ 128
#define TK 64
#define AP 68
#define AQ0 0
#define AK0 (TQ * AP)                 // 8704
#define AV0 (AK0 + TK * AP)           // 13056
#define AP0 (AV0 + TK * AP)           // 17408
#define ASMEM_U (AP0 + 8 * 16 * AP)   // 26112 u32 = 104448 B

__global__ void __launch_bounds__(256, 2) attn_tc_kernel(
    const float* __restrict__ s1, const float* __restrict__ s2,
    float* __restrict__ xo, float* __restrict__ yo)
{
    extern __shared__ uint32_t smu[];
    const int tid = threadIdx.x;
    const int lid = tid & 31;
    const int w   = tid >> 5;
    const int g   = lid >> 2;          // 0..7
    const int q   = lid & 3;           // 0..3
    const int qt  = blockIdx.x;        // 0..7
    const int b   = blockIdx.y >> 4;
    const int h   = blockIdx.y & 15;
    const int st  = blockIdx.z;

    const float* Qg = (st == 0) ? s2 : s1;
    const float* Kg = (st == 0) ? s1 : s2;
    float*       Og = (st == 0) ? xo : yo;

    const size_t plane = (size_t)BBATCH * HH * TT * DDIM;
    const size_t bh    = ((size_t)b * HH + h) * TT * DDIM;
    const float* Qb = Qg + bh + (size_t)qt * TQ * DDIM;   // kk=0
    const float* Kb = Kg + plane + bh;                    // kk=1
    const float* Vb = Kg + 2 * plane + bh;                // kk=2

    // load Q tile (128x64), already rounded: raw bit copy
    for (int i = tid; i < TQ * DDIM; i += 256)
        smu[AQ0 + (i >> 6) * AP + (i & 63)] = __float_as_uint(Qb[i]);

    float oacc[8][4];
    #pragma unroll
    for (int nt = 0; nt < 8; ++nt)
        #pragma unroll
        for (int r = 0; r < 4; ++r) oacc[nt][r] = 0.f;
    float mrow[2] = {-1e30f, -1e30f};
    float lrow[2] = {0.f, 0.f};

    uint32_t* Pw = smu + AP0 + w * 16 * AP;   // warp-private P staging
    const int mr = w * 16;

    for (int kt = 0; kt < TT / TK; ++kt) {
        __syncthreads();   // WAR: K/V tiles from previous iteration fully read
        const float* kb = Kb + (size_t)kt * TK * DDIM;
        const float* vb = Vb + (size_t)kt * TK * DDIM;
        for (int i = tid; i < TK * DDIM; i += 256) {
            const int t = i >> 6, d = i & 63;
            smu[AK0 + t * AP + d] = __float_as_uint(kb[i]);
            smu[AV0 + d * AP + t] = __float_as_uint(vb[i]);   // V transposed: d-major
        }
        __syncthreads();

        // S = Q @ K^T  (warp rows mr..mr+15, all 64 kv cols)
        float sacc[8][4];
        #pragma unroll
        for (int nt = 0; nt < 8; ++nt)
            #pragma unroll
            for (int r = 0; r < 4; ++r) sacc[nt][r] = 0.f;

        #pragma unroll
        for (int ks = 0; ks < 8; ++ks) {
            const int k0 = ks * 8;
            uint32_t af[4];
            af[0] = smu[AQ0 + (mr + g) * AP + k0 + q];
            af[1] = smu[AQ0 + (mr + g + 8) * AP + k0 + q];
            af[2] = smu[AQ0 + (mr + g) * AP + k0 + q + 4];
            af[3] = smu[AQ0 + (mr + g + 8) * AP + k0 + q + 4];
            #pragma unroll
            for (int nt = 0; nt < 8; ++nt) {
                uint32_t bf[2];
                bf[0] = smu[AK0 + (nt * 8 + g) * AP + k0 + q];
                bf[1] = smu[AK0 + (nt * 8 + g) * AP + k0 + q + 4];
                mma_tf32(sacc[nt], af, bf);
            }
        }

        // online softmax: i=0 -> row g, i=1 -> row g+8 (C frag: c[2i],c[2i+1])
        #pragma unroll
        for (int i = 0; i < 2; ++i) {
            float tm = -1e30f;
            #pragma unroll
            for (int nt = 0; nt < 8; ++nt) {
                sacc[nt][2*i]   *= 0.125f;
                sacc[nt][2*i+1] *= 0.125f;
                tm = fmaxf(tm, fmaxf(sacc[nt][2*i], sacc[nt][2*i+1]));
            }
            tm = fmaxf(tm, __shfl_xor_sync(0xffffffffu, tm, 1));
            tm = fmaxf(tm, __shfl_xor_sync(0xffffffffu, tm, 2));
            const float newm = fmaxf(mrow[i], tm);
            float rs = 0.f;
            #pragma unroll
            for (int nt = 0; nt < 8; ++nt) {
                const float p0 = __expf(sacc[nt][2*i]   - newm);
                const float p1 = __expf(sacc[nt][2*i+1] - newm);
                sacc[nt][2*i] = p0; sacc[nt][2*i+1] = p1;
                rs += p0 + p1;
            }
            rs += __shfl_xor_sync(0xffffffffu, rs, 1);
            rs += __shfl_xor_sync(0xffffffffu, rs, 2);
            const float sc = __expf(mrow[i] - newm);
            lrow[i] = lrow[i] * sc + rs;
            mrow[i] = newm;
            #pragma unroll
            for (int nt = 0; nt < 8; ++nt) {
                oacc[nt][2*i]   *= sc;
                oacc[nt][2*i+1] *= sc;
            }
        }

        // stage P as tf32 (C layout -> smem), then read back as A fragments
        #pragma unroll
        for (int nt = 0; nt < 8; ++nt) {
            Pw[g * AP + nt * 8 + 2*q]           = f2tf(sacc[nt][0]);
            Pw[g * AP + nt * 8 + 2*q + 1]       = f2tf(sacc[nt][1]);
            Pw[(g + 8) * AP + nt * 8 + 2*q]     = f2tf(sacc[nt][2]);
            Pw[(g + 8) * AP + nt * 8 + 2*q + 1] = f2tf(sacc[nt][3]);
        }
        __syncwarp();

        // O += P @ V   (B = Vs[d][t]: row.col gives sum_t P[r,t] V[t,d])
        #pragma unroll
        for (int ks = 0; ks < 8; ++ks) {
            const int k0 = ks * 8;
            uint32_t pa[4];
            pa[0] = Pw[g * AP + k0 + q];
            pa[1] = Pw[(g + 8) * AP + k0 + q];
            pa[2] = Pw[g * AP + k0 + q + 4];
            pa[3] = Pw[(g + 8) * AP + k0 + q + 4];
            #pragma unroll
            for (int nt = 0; nt < 8; ++nt) {
                uint32_t vf[2];
                vf[0] = smu[AV0 + (nt * 8 + g) * AP + k0 + q];
                vf[1] = smu[AV0 + (nt * 8 + g) * AP + k0 + q + 4];
                mma_tf32(oacc[nt], pa, vf);
            }
        }
    }

    // write O ROUNDED (out-proj loads it raw): float2 stores
    #pragma unroll
    for (int i = 0; i < 2; ++i) {
        const float inv = 1.f / lrow[i];
        const int m = qt * TQ + mr + g + 8 * i;
        float* orow = Og + ((size_t)b * TT + m) * EE + h * 64;
        #pragma unroll
        for (int nt = 0; nt < 8; ++nt) {
            float2 v;
            v.x = __uint_as_float(f2tf(oacc[nt][2*i]   * inv));
            v.y = __uint_as_float(f2tf(oacc[nt][2*i+1] * inv));
            *(float2*)(orow + nt * 8 + 2 * q) = v;
        }
    }
}

// ---------------------------------------------------------------------------
extern "C" void kernel_launch(void* const* d_in, const int* in_sizes, int n_in,
                              void* d_out, int out_size)
{
    const float* x     = (const float*)d_in[0];
    const float* y     = (const float*)d_in[1];
    const float* Wqkv1 = (const float*)d_in[2];
    const float* Wqkv2 = (const float*)d_in[3];
    const float* Wout1 = (const float*)d_in[4];
    const float* Wout2 = (const float*)d_in[5];
    float* out = (float*)d_out;

    float *s1, *s2, *xo, *yo, *rx, *ry, *rwq1, *rwq2, *rwo1, *rwo2;
    cudaGetSymbolAddress((void**)&s1, g_s1);
    cudaGetSymbolAddress((void**)&s2, g_s2);
    cudaGetSymbolAddress((void**)&xo, g_xo);
    cudaGetSymbolAddress((void**)&yo, g_yo);
    cudaGetSymbolAddress((void**)&rx, g_rx);
    cudaGetSymbolAddress((void**)&ry, g_ry);
    cudaGetSymbolAddress((void**)&rwq1, g_rwq1);
    cudaGetSymbolAddress((void**)&rwq2, g_rwq2);
    cudaGetSymbolAddress((void**)&rwo1, g_rwo1);
    cudaGetSymbolAddress((void**)&rwo2, g_rwo2);

    // Pre-round all six inputs to tf32 (idempotent; hoists cvt out of hot loops)
    const int n4_act = MTOK * EE / 4;        // 1M
    const int n4_wq  = E3 * EE / 4;          // 768K
    const int n4_wo  = EE * EE / 4;          // 256K
    round_tf32_kernel<<<(n4_act + 255) / 256, 256>>>((const float4*)x, (float4*)rx, n4_act);
    round_tf32_kernel<<<(n4_act + 255) / 256, 256>>>((const float4*)y, (float4*)ry, n4_act);
    round_tf32_kernel<<<(n4_wq  + 255) / 256, 256>>>((const float4*)Wqkv1, (float4*)rwq1, n4_wq);
    round_tf32_kernel<<<(n4_wq  + 255) / 256, 256>>>((const float4*)Wqkv2, (float4*)rwq2, n4_wq);
    round_tf32_kernel<<<(n4_wo  + 255) / 256, 256>>>((const float4*)Wout1, (float4*)rwo1, n4_wo);
    round_tf32_kernel<<<(n4_wo  + 255) / 256, 256>>>((const float4*)Wout2, (float4*)rwo2, n4_wo);

    const int gsmem = SMEM_F * sizeof(float);   // 110592
    cudaFuncSetAttribute(gemm_mma_kernel<true>,
                         cudaFuncAttributeMaxDynamicSharedMemorySize, gsmem);
    cudaFuncSetAttribute(gemm_mma_kernel<false>,
                         cudaFuncAttributeMaxDynamicSharedMemorySize, gsmem);

    // QKV projections (tf32 mma.sync) with fused split into [3][B][H][T][D]
    gemm_mma_kernel<true><<<dim3(E3 / BN, MTOK / BM), 256, gsmem>>>(rx, rwq1, s1, E3);
    gemm_mma_kernel<true><<<dim3(E3 / BN, MTOK / BM), 256, gsmem>>>(ry, rwq2, s2, E3);

    // Cross attention (tf32 mma.sync flash)
    const int asmem = ASMEM_U * sizeof(uint32_t);   // 104448
    cudaFuncSetAttribute(attn_tc_kernel,
                         cudaFuncAttributeMaxDynamicSharedMemorySize, asmem);
    attn_tc_kernel<<<dim3(TT / TQ, BBATCH * HH, 2), 256, asmem>>>(s1, s2, xo, yo);

    // Output projections (tf32 mma.sync)
    gemm_mma_kernel<false><<<dim3(EE / BN, MTOK / BM), 256, gsmem>>>(xo, rwo1, out, EE);
    gemm_mma_kernel<false><<<dim3(EE / BN, MTOK / BM), 256, gsmem>>>(yo, rwo2, out + (size_t)MTOK * EE, EE);
}

// round 14
// speedup vs baseline: 3.3139x; 1.2299x over previous
#include <cuda_runtime.h>
#include <cstdint>
#include <math.h>

#define BBATCH 4
#define TT 1024
#define EE 1024
#define HH 16
#define DDIM 64
#define E3 3072
#define MTOK (BBATCH*TT)   // 4096

// Scratch: qkv split as [3][B][H][T][D], attention outputs as (B,T,E),
// plus tf32-pre-rounded copies of all six inputs.
__device__ float g_s1[3ull * BBATCH * HH * TT * DDIM];
__device__ float g_s2[3ull * BBATCH * HH * TT * DDIM];
__device__ float g_xo[(size_t)MTOK * EE];
__device__ float g_yo[(size_t)MTOK * EE];
__device__ float g_rx[(size_t)MTOK * EE];
__device__ float g_ry[(size_t)MTOK * EE];
__device__ float g_rwq1[(size_t)E3 * EE];
__device__ float g_rwq2[(size_t)E3 * EE];
__device__ float g_rwo1[(size_t)EE * EE];
__device__ float g_rwo2[(size_t)EE * EE];

// ---------------------------------------------------------------------------
// helpers (all sm_80-level PTX: valid on plain compute_103 target)
// ---------------------------------------------------------------------------
__device__ __forceinline__ uint32_t smem_u32(const void* p) {
    uint32_t a;
    asm("{ .reg .u64 t; cvta.to.shared.u64 t, %1; cvt.u32.u64 %0, t; }" : "=r"(a) : "l"(p));
    return a;
}
__device__ __forceinline__ uint32_t f2tf(float x) {
    uint32_t r;
    asm("cvt.rna.tf32.f32 %0, %1;" : "=r"(r) : "f"(x));
    return r;
}
__device__ __forceinline__ void cp16(uint32_t dst, const void* src) {
    asm volatile("cp.async.cg.shared.global [%0], [%1], 16;" :: "r"(dst), "l"(src));
}
__device__ __forceinline__ void cp_commit() {
    asm volatile("cp.async.commit_group;" ::: "memory");
}
template<int N>
__device__ __forceinline__ void cp_wait() {
    asm volatile("cp.async.wait_group %0;" :: "n"(N) : "memory");
}
__device__ __forceinline__ void mma_tf32(float* d, const uint32_t* a, const uint32_t* b) {
    asm volatile(
        "mma.sync.aligned.m16n8k8.row.col.f32.tf32.tf32.f32 "
        "{%0,%1,%2,%3}, {%4,%5,%6,%7}, {%8,%9}, {%0,%1,%2,%3};"
        : "+f"(d[0]), "+f"(d[1]), "+f"(d[2]), "+f"(d[3])
        : "r"(a[0]), "r"(a[1]), "r"(a[2]), "r"(a[3]), "r"(b[0]), "r"(b[1]));
}

// ---------------------------------------------------------------------------
// Pre-round: dst = tf32_rna(src). Two tensors per launch (blockIdx.y).
// ---------------------------------------------------------------------------
__global__ void __launch_bounds__(256) round_tf32_kernel(
    const float4* __restrict__ s0, const float4* __restrict__ s1v,
    float4* __restrict__ d0, float4* __restrict__ d1, int n4)
{
    const float4* s = blockIdx.y ? s1v : s0;
    float4*       d = blockIdx.y ? d1  : d0;
    const int i = blockIdx.x * 256 + threadIdx.x;
    if (i < n4) {
        float4 v = s[i];
        v.x = __uint_as_float(f2tf(v.x));
        v.y = __uint_as_float(f2tf(v.y));
        v.z = __uint_as_float(f2tf(v.z));
        v.w = __uint_as_float(f2tf(v.w));
        d[i] = v;
    }
}

// ---------------------------------------------------------------------------
// mma.sync tf32 GEMM, batched over blockIdx.z (two independent GEMMs/launch):
// C(M,N) = A(M,K) @ B^T,  B stored (N,K) row-major. Pre-rounded inputs.
// 128x128x32 CTA tile, 8 warps (2x4), 3-stage cp.async pipeline.
// SPLIT: scatter tf32-ROUNDED values into [kk][b][h][t][dd] layout.
// ---------------------------------------------------------------------------
#define BM 128
#define BN 128
#define BK 32
#define PK 36
#define STAGES 3
#define NKT (EE / BK)
#define STAGE_F ((BM + BN) * PK)
#define SMEM_F (STAGES * STAGE_F)

template<bool SPLIT>
__global__ void __launch_bounds__(256, 2) gemm_mma_kernel(
    const float* __restrict__ A0, const float* __restrict__ A1,
    const float* __restrict__ B0, const float* __restrict__ B1,
    float* __restrict__ C0, float* __restrict__ C1, int N)
{
    extern __shared__ float sm[];
    const float* A = blockIdx.z ? A1 : A0;
    const float* Bm = blockIdx.z ? B1 : B0;
    float* C = blockIdx.z ? C1 : C0;

    const int tid = threadIdx.x;
    const int lid = tid & 31;
    const int wid = tid >> 5;
    const int warp_m = wid & 1;
    const int warp_n = wid >> 1;
    const int g = lid >> 2;
    const int q = lid & 3;
    const int row0 = blockIdx.y * BM;
    const int col0 = blockIdx.x * BN;

    const uint32_t sbase = smem_u32(sm);

    auto issue = [&](int stg, int kt) {
        const uint32_t s_a = sbase + (uint32_t)(stg * STAGE_F) * 4u;
        const uint32_t s_b = s_a + (uint32_t)(BM * PK) * 4u;
        #pragma unroll
        for (int i = 0; i < 4; ++i) {
            const int idx = tid + 256 * i;
            const int r = idx >> 3;
            const int c = (idx & 7) * 4;
            cp16(s_a + (uint32_t)(r * PK + c) * 4u,
                 A + (size_t)(row0 + r) * EE + kt * BK + c);
            cp16(s_b + (uint32_t)(r * PK + c) * 4u,
                 Bm + (size_t)(col0 + r) * EE + kt * BK + c);
        }
    };

    float acc[4][4][4];
    #pragma unroll
    for (int i = 0; i < 4; ++i)
        #pragma unroll
        for (int j = 0; j < 4; ++j)
            #pragma unroll
            for (int r = 0; r < 4; ++r) acc[i][j][r] = 0.f;

    #pragma unroll
    for (int s = 0; s < STAGES - 1; ++s) { issue(s, s); cp_commit(); }

    for (int kt = 0; kt < NKT; ++kt) {
        if (kt < NKT - 1) cp_wait<1>(); else cp_wait<0>();
        __syncthreads();

        if (kt + STAGES - 1 < NKT) {
            issue((kt + STAGES - 1) % STAGES, kt + STAGES - 1);
            cp_commit();
        }

        const float* as = sm + (kt % STAGES) * STAGE_F;
        const float* bs = as + BM * PK;

        #pragma unroll
        for (int ks = 0; ks < 4; ++ks) {
            const int k0 = ks * 8;
            uint32_t af[4][4], bf[4][2];
            #pragma unroll
            for (int im = 0; im < 4; ++im) {
                const int mr = warp_m * 64 + im * 16 + g;
                af[im][0] = __float_as_uint(as[mr * PK + k0 + q]);
                af[im][1] = __float_as_uint(as[(mr + 8) * PK + k0 + q]);
                af[im][2] = __float_as_uint(as[mr * PK + k0 + q + 4]);
                af[im][3] = __float_as_uint(as[(mr + 8) * PK + k0 + q + 4]);
            }
            #pragma unroll
            for (int jn = 0; jn < 4; ++jn) {
                const int nc = warp_n * 32 + jn * 8 + g;
                bf[jn][0] = __float_as_uint(bs[nc * PK + k0 + q]);
                bf[jn][1] = __float_as_uint(bs[nc * PK + k0 + q + 4]);
            }
            #pragma unroll
            for (int im = 0; im < 4; ++im)
                #pragma unroll
                for (int jn = 0; jn < 4; ++jn)
                    mma_tf32(acc[im][jn], af[im], bf[jn]);
        }
    }

    #pragma unroll
    for (int im = 0; im < 4; ++im) {
        #pragma unroll
        for (int jn = 0; jn < 4; ++jn) {
            const int mrow = row0 + warp_m * 64 + im * 16 + g;
            const int ncol = col0 + warp_n * 32 + jn * 8 + 2 * q;
            #pragma unroll
            for (int rg = 0; rg < 4; ++rg) {
                const int m = mrow + ((rg >> 1) << 3);
                const int n = ncol + (rg & 1);
                if (SPLIT) {
                    const int dd = n / 48;
                    const int rr = n - dd * 48;
                    const int kk = rr >> 4;
                    const int hh = rr & 15;
                    const int bb = m >> 10;
                    const int t  = m & 1023;
                    C[((((size_t)kk * BBATCH + bb) * HH + hh) * TT + t) * DDIM + dd] =
                        __uint_as_float(f2tf(acc[im][jn][rg]));
                } else {
                    C[(size_t)m * N + n] = acc[im][jn][rg];
                }
            }
        }
    }
}

// ---------------------------------------------------------------------------
// Dual-stream cross attention, mma.sync tf32.
// 4 warps (128 threads), each warp owns 32 q-rows (im=2) -> B-fragments
// reused across 2x mma (halves smem crossbar traffic vs 16-row warps).
// Q/K natural [t][d] pitch 68 (frag banks 4g+q: conflict-free).
// V natural [t][d] pitch 72 (frag banks 8q+g: conflict-free, no transpose).
// All tile loads: LDG.128 + STS.128 conflict-free; next K/V register-prefetched.
// ---------------------------------------------------------------------------
#define TQ 128
#define TK 64
#define APQ 68
#define APV 72
#define AQ0 0
#define AK0 (TQ * APQ)                 // 8704
#define AV0 (AK0 + TK * APQ)           // 13056
#define AP0 (AV0 + TK * APV)           // 17664
#define ASMEM_U (AP0 + 4 * 32 * APQ)   // 26368 u32 = 105472 B

__global__ void __launch_bounds__(128, 2) attn_tc_kernel(
    const float* __restrict__ s1, const float* __restrict__ s2,
    float* __restrict__ xo, float* __restrict__ yo)
{
    extern __shared__ uint32_t smu[];
    const int tid = threadIdx.x;
    const int lid = tid & 31;
    const int w   = tid >> 5;          // 0..3
    const int g   = lid >> 2;          // 0..7
    const int q   = lid & 3;           // 0..3
    const int qt  = blockIdx.x;        // 0..7
    const int b   = blockIdx.y >> 4;
    const int h   = blockIdx.y & 15;
    const int st  = blockIdx.z;

    const float* Qg = (st == 0) ? s2 : s1;
    const float* Kg = (st == 0) ? s1 : s2;
    float*       Og = (st == 0) ? xo : yo;

    const size_t plane = (size_t)BBATCH * HH * TT * DDIM;
    const size_t bh    = ((size_t)b * HH + h) * TT * DDIM;
    const float* Qb = Qg + bh + (size_t)qt * TQ * DDIM;   // kk=0
    const float* Kb = Kg + plane + bh;                    // kk=1
    const float* Vb = Kg + 2 * plane + bh;                // kk=2

    // load Q tile (128x64, pre-rounded): float4, STS.128 conflict-free
    {
        const float4* qb4 = (const float4*)Qb;
        #pragma unroll
        for (int i = 0; i < 16; ++i) {
            const int j = tid + 128 * i;          // 0..2047
            const int t = j >> 4, d = (j & 15) * 4;
            *reinterpret_cast<float4*>(&smu[AQ0 + t * APQ + d]) = qb4[j];
        }
    }

    float oacc[2][8][4];
    #pragma unroll
    for (int im = 0; im < 2; ++im)
        #pragma unroll
        for (int nt = 0; nt < 8; ++nt)
            #pragma unroll
            for (int r = 0; r < 4; ++r) oacc[im][nt][r] = 0.f;
    float mrow[2][2] = {{-1e30f, -1e30f}, {-1e30f, -1e30f}};
    float lrow[2][2] = {{0.f, 0.f}, {0.f, 0.f}};

    uint32_t* Pw = smu + AP0 + w * 32 * APQ;   // warp-private P staging (32 rows)
    const int mr = w * 32;

    // K/V register prefetch buffers (8 float4 each)
    float4 kreg[8], vreg[8];
    auto ldkv = [&](int kt) {
        const float4* kb4 = (const float4*)(Kb + (size_t)kt * TK * DDIM);
        const float4* vb4 = (const float4*)(Vb + (size_t)kt * TK * DDIM);
        #pragma unroll
        for (int i = 0; i < 8; ++i) {
            kreg[i] = kb4[tid + 128 * i];
            vreg[i] = vb4[tid + 128 * i];
        }
    };
    ldkv(0);

    for (int kt = 0; kt < TT / TK; ++kt) {
        __syncthreads();   // WAR: previous iteration's readers done
        #pragma unroll
        for (int i = 0; i < 8; ++i) {
            const int j = tid + 128 * i;          // 0..1023
            const int t = j >> 4, d = (j & 15) * 4;
            *reinterpret_cast<float4*>(&smu[AK0 + t * APQ + d]) = kreg[i];
            *reinterpret_cast<float4*>(&smu[AV0 + t * APV + d]) = vreg[i];
        }
        __syncthreads();
        if (kt + 1 < TT / TK) ldkv(kt + 1);   // hidden behind compute

        // S = Q @ K^T  (warp rows mr..mr+31, all 64 kv cols)
        float sacc[2][8][4];
        #pragma unroll
        for (int im = 0; im < 2; ++im)
            #pragma unroll
            for (int nt = 0; nt < 8; ++nt)
                #pragma unroll
                for (int r = 0; r < 4; ++r) sacc[im][nt][r] = 0.f;

        #pragma unroll
        for (int ks = 0; ks < 8; ++ks) {
            const int k0 = ks * 8;
            uint32_t af[2][4];
            #pragma unroll
            for (int im = 0; im < 2; ++im) {
                const int row = mr + 16 * im;
                af[im][0] = smu[AQ0 + (row + g) * APQ + k0 + q];
                af[im][1] = smu[AQ0 + (row + g + 8) * APQ + k0 + q];
                af[im][2] = smu[AQ0 + (row + g) * APQ + k0 + q + 4];
                af[im][3] = smu[AQ0 + (row + g + 8) * APQ + k0 + q + 4];
            }
            #pragma unroll
            for (int nt = 0; nt < 8; ++nt) {
                uint32_t bf[2];
                bf[0] = smu[AK0 + (nt * 8 + g) * APQ + k0 + q];
                bf[1] = smu[AK0 + (nt * 8 + g) * APQ + k0 + q + 4];
                mma_tf32(sacc[0][nt], af[0], bf);
                mma_tf32(sacc[1][nt], af[1], bf);
            }
        }

        // online softmax: rows mr + 16*im + 8*i + g (C frag: c[2i], c[2i+1])
        #pragma unroll
        for (int im = 0; im < 2; ++im) {
            #pragma unroll
            for (int i = 0; i < 2; ++i) {
                float tm = -1e30f;
                #pragma unroll
                for (int nt = 0; nt < 8; ++nt) {
                    sacc[im][nt][2*i]   *= 0.125f;
                    sacc[im][nt][2*i+1] *= 0.125f;
                    tm = fmaxf(tm, fmaxf(sacc[im][nt][2*i], sacc[im][nt][2*i+1]));
                }
                tm = fmaxf(tm, __shfl_xor_sync(0xffffffffu, tm, 1));
                tm = fmaxf(tm, __shfl_xor_sync(0xffffffffu, tm, 2));
                const float newm = fmaxf(mrow[im][i], tm);
                float rs = 0.f;
                #pragma unroll
                for (int nt = 0; nt < 8; ++nt) {
                    const float p0 = __expf(sacc[im][nt][2*i]   - newm);
                    const float p1 = __expf(sacc[im][nt][2*i+1] - newm);
                    sacc[im][nt][2*i] = p0; sacc[im][nt][2*i+1] = p1;
                    rs += p0 + p1;
                }
                rs += __shfl_xor_sync(0xffffffffu, rs, 1);
                rs += __shfl_xor_sync(0xffffffffu, rs, 2);
                const float sc = __expf(mrow[im][i] - newm);
                lrow[im][i] = lrow[im][i] * sc + rs;
                mrow[im][i] = newm;
                #pragma unroll
                for (int nt = 0; nt < 8; ++nt) {
                    oacc[im][nt][2*i]   *= sc;
                    oacc[im][nt][2*i+1] *= sc;
                }
            }
        }

        // stage P as tf32 (C layout -> smem), read back as A fragments
        #pragma unroll
        for (int im = 0; im < 2; ++im) {
            const int r0 = 16 * im;
            #pragma unroll
            for (int nt = 0; nt < 8; ++nt) {
                Pw[(r0 + g) * APQ + nt * 8 + 2*q]           = f2tf(sacc[im][nt][0]);
                Pw[(r0 + g) * APQ + nt * 8 + 2*q + 1]       = f2tf(sacc[im][nt][1]);
                Pw[(r0 + g + 8) * APQ + nt * 8 + 2*q]       = f2tf(sacc[im][nt][2]);
                Pw[(r0 + g + 8) * APQ + nt * 8 + 2*q + 1]   = f2tf(sacc[im][nt][3]);
            }
        }
        __syncwarp();

        // O += P @ V  (V natural [t][d]: B[k=t][n=d] at (k0+q)*APV + d, banks 8q+g)
        #pragma unroll
        for (int ks = 0; ks < 8; ++ks) {
            const int k0 = ks * 8;
            uint32_t pa[2][4];
            #pragma unroll
            for (int im = 0; im < 2; ++im) {
                const int r0 = 16 * im;
                pa[im][0] = Pw[(r0 + g) * APQ + k0 + q];
                pa[im][1] = Pw[(r0 + g + 8) * APQ + k0 + q];
                pa[im][2] = Pw[(r0 + g) * APQ + k0 + q + 4];
                pa[im][3] = Pw[(r0 + g + 8) * APQ + k0 + q + 4];
            }
            #pragma unroll
            for (int nt = 0; nt < 8; ++nt) {
                uint32_t vf[2];
                vf[0] = smu[AV0 + (k0 + q) * APV + nt * 8 + g];
                vf[1] = smu[AV0 + (k0 + q + 4) * APV + nt * 8 + g];
                mma_tf32(oacc[0][nt], pa[0], vf);
                mma_tf32(oacc[1][nt], pa[1], vf);
            }
        }
    }

    // write O ROUNDED (out-proj loads it raw): float2 stores
    #pragma unroll
    for (int im = 0; im < 2; ++im) {
        #pragma unroll
        for (int i = 0; i < 2; ++i) {
            const float inv = 1.f / lrow[im][i];
            const int m = qt * TQ + mr + 16 * im + 8 * i + g;
            float* orow = Og + ((size_t)b * TT + m) * EE + h * 64;
            #pragma unroll
            for (int nt = 0; nt < 8; ++nt) {
                float2 v;
                v.x = __uint_as_float(f2tf(oacc[im][nt][2*i]   * inv));
                v.y = __uint_as_float(f2tf(oacc[im][nt][2*i+1] * inv));
                *(float2*)(orow + nt * 8 + 2 * q) = v;
            }
        }
    }
}

// ---------------------------------------------------------------------------
extern "C" void kernel_launch(void* const* d_in, const int* in_sizes, int n_in,
                              void* d_out, int out_size)
{
    const float* x     = (const float*)d_in[0];
    const float* y     = (const float*)d_in[1];
    const float* Wqkv1 = (const float*)d_in[2];
    const float* Wqkv2 = (const float*)d_in[3];
    const float* Wout1 = (const float*)d_in[4];
    const float* Wout2 = (const float*)d_in[5];
    float* out = (float*)d_out;

    float *s1, *s2, *xo, *yo, *rx, *ry, *rwq1, *rwq2, *rwo1, *rwo2;
    cudaGetSymbolAddress((void**)&s1, g_s1);
    cudaGetSymbolAddress((void**)&s2, g_s2);
    cudaGetSymbolAddress((void**)&xo, g_xo);
    cudaGetSymbolAddress((void**)&yo, g_yo);
    cudaGetSymbolAddress((void**)&rx, g_rx);
    cudaGetSymbolAddress((void**)&ry, g_ry);
    cudaGetSymbolAddress((void**)&rwq1, g_rwq1);
    cudaGetSymbolAddress((void**)&rwq2, g_rwq2);
    cudaGetSymbolAddress((void**)&rwo1, g_rwo1);
    cudaGetSymbolAddress((void**)&rwo2, g_rwo2);

    // Pre-round all six inputs to tf32 (paired launches)
    const int n4_act = MTOK * EE / 4;        // 1M
    const int n4_wq  = E3 * EE / 4;          // 768K
    const int n4_wo  = EE * EE / 4;          // 256K
    round_tf32_kernel<<<dim3((n4_act + 255) / 256, 2), 256>>>(
        (const float4*)x, (const float4*)y, (float4*)rx, (float4*)ry, n4_act);
    round_tf32_kernel<<<dim3((n4_wq + 255) / 256, 2), 256>>>(
        (const float4*)Wqkv1, (const float4*)Wqkv2, (float4*)rwq1, (float4*)rwq2, n4_wq);
    round_tf32_kernel<<<dim3((n4_wo + 255) / 256, 2), 256>>>(
        (const float4*)Wout1, (const float4*)Wout2, (float4*)rwo1, (float4*)rwo2, n4_wo);

    const int gsmem = SMEM_F * sizeof(float);   // 110592
    cudaFuncSetAttribute(gemm_mma_kernel<true>,
                         cudaFuncAttributeMaxDynamicSharedMemorySize, gsmem);
    cudaFuncSetAttribute(gemm_mma_kernel<false>,
                         cudaFuncAttributeMaxDynamicSharedMemorySize, gsmem);

    // QKV projections for BOTH streams in one launch (z=2)
    gemm_mma_kernel<true><<<dim3(E3 / BN, MTOK / BM, 2), 256, gsmem>>>(
        rx, ry, rwq1, rwq2, s1, s2, E3);

    // Cross attention (tf32 mma.sync flash, 128 threads, 32-row warps)
    const int asmem = ASMEM_U * sizeof(uint32_t);   // 105472
    cudaFuncSetAttribute(attn_tc_kernel,
                         cudaFuncAttributeMaxDynamicSharedMemorySize, asmem);
    attn_tc_kernel<<<dim3(TT / TQ, BBATCH * HH, 2), 128, asmem>>>(s1, s2, xo, yo);

    // Output projections for BOTH streams in one launch (z=2)
    gemm_mma_kernel<false><<<dim3(EE / BN, MTOK / BM, 2), 256, gsmem>>>(
        xo, yo, rwo1, rwo2, out, out + (size_t)MTOK * EE, EE);
}

// round 16
// speedup vs baseline: 4.7076x; 1.4206x over previous
#include <cuda_runtime.h>
#include <cuda_fp16.h>
#include <cstdint>
#include <math.h>

#define BBATCH 4
#define TT 1024
#define EE 1024
#define HH 16
#define DDIM 64
#define E3 3072
#define MTOK (BBATCH*TT)   // 4096

// Scratch (fp16): qkv split [3][B][H][T][D], attention outputs (B,T,E),
// pre-converted fp16 copies of all six inputs.
__device__ __half g_s1[3ull * BBATCH * HH * TT * DDIM];
__device__ __half g_s2[3ull * BBATCH * HH * TT * DDIM];
__device__ __half g_xo[(size_t)MTOK * EE];
__device__ __half g_yo[(size_t)MTOK * EE];
__device__ __half g_hx[(size_t)MTOK * EE];
__device__ __half g_hy[(size_t)MTOK * EE];
__device__ __half g_hwq1[(size_t)E3 * EE];
__device__ __half g_hwq2[(size_t)E3 * EE];
__device__ __half g_hwo1[(size_t)EE * EE];
__device__ __half g_hwo2[(size_t)EE * EE];

// ---------------------------------------------------------------------------
// helpers (sm_75/80-level PTX: valid on plain compute_103 target)
// ---------------------------------------------------------------------------
__device__ __forceinline__ uint32_t smem_u32(const void* p) {
    uint32_t a;
    asm("{ .reg .u64 t; cvta.to.shared.u64 t, %1; cvt.u32.u64 %0, t; }" : "=r"(a) : "l"(p));
    return a;
}
__device__ __forceinline__ void cp16(uint32_t dst, const void* src) {
    asm volatile("cp.async.cg.shared.global [%0], [%1], 16;" :: "r"(dst), "l"(src));
}
__device__ __forceinline__ void cp_commit() {
    asm volatile("cp.async.commit_group;" ::: "memory");
}
template<int N>
__device__ __forceinline__ void cp_wait() {
    asm volatile("cp.async.wait_group %0;" :: "n"(N) : "memory");
}
__device__ __forceinline__ void mma_f16(float* d, const uint32_t* a, const uint32_t* b) {
    asm volatile(
        "mma.sync.aligned.m16n8k16.row.col.f32.f16.f16.f32 "
        "{%0,%1,%2,%3}, {%4,%5,%6,%7}, {%8,%9}, {%0,%1,%2,%3};"
        : "+f"(d[0]), "+f"(d[1]), "+f"(d[2]), "+f"(d[3])
        : "r"(a[0]), "r"(a[1]), "r"(a[2]), "r"(a[3]), "r"(b[0]), "r"(b[1]));
}
__device__ __forceinline__ void ldmx4t(uint32_t& r0, uint32_t& r1, uint32_t& r2,
                                       uint32_t& r3, uint32_t addr) {
    asm volatile("ldmatrix.sync.aligned.m8n8.x4.trans.shared.b16 {%0,%1,%2,%3}, [%4];"
        : "=r"(r0), "=r"(r1), "=r"(r2), "=r"(r3) : "r"(addr));
}
__device__ __forceinline__ uint32_t pack_h2(float a, float b) {
    __half2 h = __floats2half2_rn(a, b);   // .x = a (lo), .y = b (hi)
    return *(uint32_t*)&h;
}

// ---------------------------------------------------------------------------
// Pre-convert fp32 -> fp16 (RN). Two tensors per launch (blockIdx.y).
// ---------------------------------------------------------------------------
__global__ void __launch_bounds__(256) cvt_h_kernel(
    const float4* __restrict__ s0, const float4* __restrict__ s1v,
    uint2* __restrict__ d0, uint2* __restrict__ d1, int n4)
{
    const float4* s = blockIdx.y ? s1v : s0;
    uint2*        d = blockIdx.y ? d1  : d0;
    const int i = blockIdx.x * 256 + threadIdx.x;
    if (i < n4) {
        float4 v = s[i];
        uint2 o;
        o.x = pack_h2(v.x, v.y);
        o.y = pack_h2(v.z, v.w);
        d[i] = o;
    }
}

// ---------------------------------------------------------------------------
// fp16 mma.sync GEMM, batched over blockIdx.z:  C = A(M,K) @ B^T (B = (N,K)).
// 128x128x64(half) CTA tile, 8 warps (2x4), 3-stage cp.async pipeline.
// Half pitch 72 (word pitch 36 == 4 mod 32): fragment LDS + STS conflict-free.
// SPLIT: scatter fp16 into [kk][b][h][t][dd]; else fp32 C.
// ---------------------------------------------------------------------------
#define BM 128
#define BN 128
#define BKH 64
#define PKH 72
#define PKW 36
#define NKT16 (EE / BKH)               // 16
#define STAGE_H ((BM + BN) * PKH)      // 18432 halves
#define GSMEM_B (3 * STAGE_H * 2)      // 110592 B

template<bool SPLIT>
__global__ void __launch_bounds__(256, 2) gemm_f16_kernel(
    const __half* __restrict__ A0, const __half* __restrict__ A1,
    const __half* __restrict__ B0, const __half* __restrict__ B1,
    void* __restrict__ C0, void* __restrict__ C1, int N)
{
    extern __shared__ char smc[];
    uint32_t* smw = (uint32_t*)smc;
    const __half* A = blockIdx.z ? A1 : A0;
    const __half* Bm = blockIdx.z ? B1 : B0;
    void* C = blockIdx.z ? C1 : C0;

    const int tid = threadIdx.x;
    const int lid = tid & 31;
    const int wid = tid >> 5;
    const int warp_m = wid & 1;
    const int warp_n = wid >> 1;
    const int g = lid >> 2;
    const int q = lid & 3;
    const int row0 = blockIdx.y * BM;
    const int col0 = blockIdx.x * BN;

    const uint32_t sbase = smem_u32(smc);

    auto issue = [&](int stg, int kt) {
        const uint32_t s_a = sbase + (uint32_t)(stg * STAGE_H) * 2u;
        const uint32_t s_b = s_a + (uint32_t)(BM * PKH) * 2u;
        #pragma unroll
        for (int i = 0; i < 4; ++i) {
            const int idx = tid + 256 * i;          // 0..1023
            const int r = idx >> 3;                 // row 0..127
            const int c = (idx & 7) * 8;            // half col 0,8,..,56
            cp16(s_a + (uint32_t)(r * PKH + c) * 2u,
                 A + (size_t)(row0 + r) * EE + kt * BKH + c);
            cp16(s_b + (uint32_t)(r * PKH + c) * 2u,
                 Bm + (size_t)(col0 + r) * EE + kt * BKH + c);
        }
    };

    float acc[4][4][4];
    #pragma unroll
    for (int i = 0; i < 4; ++i)
        #pragma unroll
        for (int j = 0; j < 4; ++j)
            #pragma unroll
            for (int r = 0; r < 4; ++r) acc[i][j][r] = 0.f;

    #pragma unroll
    for (int s = 0; s < 2; ++s) { issue(s, s); cp_commit(); }

    for (int kt = 0; kt < NKT16; ++kt) {
        if (kt < NKT16 - 1) cp_wait<1>(); else cp_wait<0>();
        __syncthreads();

        if (kt + 2 < NKT16) { issue((kt + 2) % 3, kt + 2); cp_commit(); }

        const uint32_t* as = smw + (kt % 3) * (STAGE_H / 2);
        const uint32_t* bs = as + BM * PKW;

        #pragma unroll
        for (int ks = 0; ks < 4; ++ks) {
            const int k0 = ks * 8;                  // word offset within row
            uint32_t af[4][4], bf[4][2];
            #pragma unroll
            for (int im = 0; im < 4; ++im) {
                const int mr = warp_m * 64 + im * 16 + g;
                af[im][0] = as[mr * PKW + k0 + q];
                af[im][1] = as[(mr + 8) * PKW + k0 + q];
                af[im][2] = as[mr * PKW + k0 + q + 4];
                af[im][3] = as[(mr + 8) * PKW + k0 + q + 4];
            }
            #pragma unroll
            for (int jn = 0; jn < 4; ++jn) {
                const int nc = warp_n * 32 + jn * 8 + g;
                bf[jn][0] = bs[nc * PKW + k0 + q];
                bf[jn][1] = bs[nc * PKW + k0 + q + 4];
            }
            #pragma unroll
            for (int im = 0; im < 4; ++im)
                #pragma unroll
                for (int jn = 0; jn < 4; ++jn)
                    mma_f16(acc[im][jn], af[im], bf[jn]);
        }
    }

    #pragma unroll
    for (int im = 0; im < 4; ++im) {
        #pragma unroll
        for (int jn = 0; jn < 4; ++jn) {
            const int mrow = row0 + warp_m * 64 + im * 16 + g;
            const int ncol = col0 + warp_n * 32 + jn * 8 + 2 * q;
            #pragma unroll
            for (int rg = 0; rg < 4; ++rg) {
                const int m = mrow + ((rg >> 1) << 3);
                const int n = ncol + (rg & 1);
                if (SPLIT) {
                    const int dd = n / 48;
                    const int rr = n - dd * 48;
                    const int kk = rr >> 4;
                    const int hh = rr & 15;
                    const int bb = m >> 10;
                    const int t  = m & 1023;
                    ((__half*)C)[((((size_t)kk * BBATCH + bb) * HH + hh) * TT + t) * DDIM + dd] =
                        __float2half_rn(acc[im][jn][rg]);
                } else {
                    ((float*)C)[(size_t)m * N + n] = acc[im][jn][rg];
                }
            }
        }
    }
}

// ---------------------------------------------------------------------------
// Dual-stream cross attention, fp16 mma.sync m16n8k16.
// 4 warps (128 thr), each warp 32 q-rows. Q/K/V natural [t][d] halves, word
// pitch 36 (conflict-free frags + STS.128). V B-frags via ldmatrix.x4.trans.
// P staged as packed half2. Outputs written fp16.
// ---------------------------------------------------------------------------
#define TQ 128
#define TK 64
#define AQ0 0
#define AK0 (TQ * PKW)                 // 4608 words
#define AV0 (AK0 + TK * PKW)           // 6912
#define AP0 (AV0 + TK * PKW)           // 9216
#define ASMW (AP0 + 4 * 32 * PKW)      // 13824 words = 55296 B

__global__ void __launch_bounds__(128, 2) attn_tc_kernel(
    const __half* __restrict__ s1, const __half* __restrict__ s2,
    __half* __restrict__ xo, __half* __restrict__ yo)
{
    extern __shared__ uint32_t smu[];
    const int tid = threadIdx.x;
    const int lid = tid & 31;
    const int w   = tid >> 5;          // 0..3
    const int g   = lid >> 2;          // 0..7
    const int q   = lid & 3;           // 0..3
    const int qt  = blockIdx.x;        // 0..7
    const int b   = blockIdx.y >> 4;
    const int h   = blockIdx.y & 15;
    const int st  = blockIdx.z;

    const __half* Qg = (st == 0) ? s2 : s1;
    const __half* Kg = (st == 0) ? s1 : s2;
    __half*       Og = (st == 0) ? xo : yo;

    const size_t plane = (size_t)BBATCH * HH * TT * DDIM;
    const size_t bh    = ((size_t)b * HH + h) * TT * DDIM;
    const __half* Qb = Qg + bh + (size_t)qt * TQ * DDIM;   // kk=0
    const __half* Kb = Kg + plane + bh;                    // kk=1
    const __half* Vb = Kg + 2 * plane + bh;                // kk=2

    const uint32_t vbase = smem_u32(smu) + AV0 * 4;

    // ldmatrix per-lane row/col selector (x4.trans over V[t][d])
    const int sel = lid >> 3;                  // 0..3
    const int lr8 = lid & 7;
    const int vrow = lr8 + ((sel & 1) << 3);   // row within 16-row k-block
    const int vcolw = (sel >> 1) << 2;         // +0 or +4 words (d-block parity)

    // load Q tile (128x64 halves): float4 chunks, STS.128 conflict-free
    {
        const float4* qb4 = (const float4*)Qb;
        #pragma unroll
        for (int i = 0; i < 8; ++i) {
            const int j = tid + 128 * i;            // 0..1023
            const int t = j >> 3, cw = (j & 7) * 4; // word col
            *reinterpret_cast<float4*>(&smu[AQ0 + t * PKW + cw]) = qb4[j];
        }
    }

    float oacc[2][8][4];
    #pragma unroll
    for (int im = 0; im < 2; ++im)
        #pragma unroll
        for (int nt = 0; nt < 8; ++nt)
            #pragma unroll
            for (int r = 0; r < 4; ++r) oacc[im][nt][r] = 0.f;
    float mrow[2][2] = {{-1e30f, -1e30f}, {-1e30f, -1e30f}};
    float lrow[2][2] = {{0.f, 0.f}, {0.f, 0.f}};

    uint32_t* Pw = smu + AP0 + w * 32 * PKW;
    const int mr = w * 32;

    float4 kreg[4], vreg[4];
    auto ldkv = [&](int kt) {
        const float4* kb4 = (const float4*)(Kb + (size_t)kt * TK * DDIM);
        const float4* vb4 = (const float4*)(Vb + (size_t)kt * TK * DDIM);
        #pragma unroll
        for (int i = 0; i < 4; ++i) {
            kreg[i] = kb4[tid + 128 * i];
            vreg[i] = vb4[tid + 128 * i];
        }
    };
    ldkv(0);

    for (int kt = 0; kt < TT / TK; ++kt) {
        __syncthreads();
        #pragma unroll
        for (int i = 0; i < 4; ++i) {
            const int j = tid + 128 * i;            // 0..511
            const int t = j >> 3, cw = (j & 7) * 4;
            *reinterpret_cast<float4*>(&smu[AK0 + t * PKW + cw]) = kreg[i];
            *reinterpret_cast<float4*>(&smu[AV0 + t * PKW + cw]) = vreg[i];
        }
        __syncthreads();
        if (kt + 1 < TT / TK) ldkv(kt + 1);

        // S = Q @ K^T
        float sacc[2][8][4];
        #pragma unroll
        for (int im = 0; im < 2; ++im)
            #pragma unroll
            for (int nt = 0; nt < 8; ++nt)
                #pragma unroll
                for (int r = 0; r < 4; ++r) sacc[im][nt][r] = 0.f;

        #pragma unroll
        for (int ks = 0; ks < 4; ++ks) {
            const int k0 = ks * 8;                  // word offset
            uint32_t af[2][4];
            #pragma unroll
            for (int im = 0; im < 2; ++im) {
                const int row = mr + 16 * im;
                af[im][0] = smu[AQ0 + (row + g) * PKW + k0 + q];
                af[im][1] = smu[AQ0 + (row + g + 8) * PKW + k0 + q];
                af[im][2] = smu[AQ0 + (row + g) * PKW + k0 + q + 4];
                af[im][3] = smu[AQ0 + (row + g + 8) * PKW + k0 + q + 4];
            }
            #pragma unroll
            for (int nt = 0; nt < 8; ++nt) {
                uint32_t bf[2];
                bf[0] = smu[AK0 + (nt * 8 + g) * PKW + k0 + q];
                bf[1] = smu[AK0 + (nt * 8 + g) * PKW + k0 + q + 4];
                mma_f16(sacc[0][nt], af[0], bf);
                mma_f16(sacc[1][nt], af[1], bf);
            }
        }

        // online softmax
        #pragma unroll
        for (int im = 0; im < 2; ++im) {
            #pragma unroll
            for (int i = 0; i < 2; ++i) {
                float tm = -1e30f;
                #pragma unroll
                for (int nt = 0; nt < 8; ++nt) {
                    sacc[im][nt][2*i]   *= 0.125f;
                    sacc[im][nt][2*i+1] *= 0.125f;
                    tm = fmaxf(tm, fmaxf(sacc[im][nt][2*i], sacc[im][nt][2*i+1]));
                }
                tm = fmaxf(tm, __shfl_xor_sync(0xffffffffu, tm, 1));
                tm = fmaxf(tm, __shfl_xor_sync(0xffffffffu, tm, 2));
                const float newm = fmaxf(mrow[im][i], tm);
                float rs = 0.f;
                #pragma unroll
                for (int nt = 0; nt < 8; ++nt) {
                    const float p0 = __expf(sacc[im][nt][2*i]   - newm);
                    const float p1 = __expf(sacc[im][nt][2*i+1] - newm);
                    sacc[im][nt][2*i] = p0; sacc[im][nt][2*i+1] = p1;
                    rs += p0 + p1;
                }
                rs += __shfl_xor_sync(0xffffffffu, rs, 1);
                rs += __shfl_xor_sync(0xffffffffu, rs, 2);
                const float sc = __expf(mrow[im][i] - newm);
                lrow[im][i] = lrow[im][i] * sc + rs;
                mrow[im][i] = newm;
                #pragma unroll
                for (int nt = 0; nt < 8; ++nt) {
                    oacc[im][nt][2*i]   *= sc;
                    oacc[im][nt][2*i+1] *= sc;
                }
            }
        }

        // stage P as packed half2 (C layout -> A layout)
        #pragma unroll
        for (int im = 0; im < 2; ++im) {
            const int r0 = 16 * im;
            #pragma unroll
            for (int nt = 0; nt < 8; ++nt) {
                Pw[(r0 + g) * PKW + nt * 4 + q]     = pack_h2(sacc[im][nt][0], sacc[im][nt][1]);
                Pw[(r0 + g + 8) * PKW + nt * 4 + q] = pack_h2(sacc[im][nt][2], sacc[im][nt][3]);
            }
        }
        __syncwarp();

        // O += P @ V  (V frags via ldmatrix.x4.trans on natural [t][d])
        #pragma unroll
        for (int ks = 0; ks < 4; ++ks) {
            const int k0 = ks * 8;
            uint32_t pa[2][4];
            #pragma unroll
            for (int im = 0; im < 2; ++im) {
                const int r0 = 16 * im;
                pa[im][0] = Pw[(r0 + g) * PKW + k0 + q];
                pa[im][1] = Pw[(r0 + g + 8) * PKW + k0 + q];
                pa[im][2] = Pw[(r0 + g) * PKW + k0 + q + 4];
                pa[im][3] = Pw[(r0 + g + 8) * PKW + k0 + q + 4];
            }
            const uint32_t arow = vbase + (uint32_t)((ks * 16 + vrow) * PKW) * 4u;
            #pragma unroll
            for (int ntp = 0; ntp < 4; ++ntp) {
                uint32_t v0, v1, v2, v3;
                ldmx4t(v0, v1, v2, v3, arow + (uint32_t)(ntp * 8 + vcolw) * 4u);
                uint32_t bfa[2] = {v0, v1}, bfb[2] = {v2, v3};
                mma_f16(oacc[0][2*ntp],     pa[0], bfa);
                mma_f16(oacc[1][2*ntp],     pa[1], bfa);
                mma_f16(oacc[0][2*ntp + 1], pa[0], bfb);
                mma_f16(oacc[1][2*ntp + 1], pa[1], bfb);
            }
        }
    }

    // write O as fp16 (half2 stores)
    #pragma unroll
    for (int im = 0; im < 2; ++im) {
        #pragma unroll
        for (int i = 0; i < 2; ++i) {
            const float inv = 1.f / lrow[im][i];
            const int m = qt * TQ + mr + 16 * im + 8 * i + g;
            __half* orow = Og + ((size_t)b * TT + m) * EE + h * 64;
            #pragma unroll
            for (int nt = 0; nt < 8; ++nt) {
                uint32_t hv = pack_h2(oacc[im][nt][2*i] * inv, oacc[im][nt][2*i+1] * inv);
                *(uint32_t*)(orow + nt * 8 + 2 * q) = hv;
            }
        }
    }
}

// ---------------------------------------------------------------------------
extern "C" void kernel_launch(void* const* d_in, const int* in_sizes, int n_in,
                              void* d_out, int out_size)
{
    const float* x     = (const float*)d_in[0];
    const float* y     = (const float*)d_in[1];
    const float* Wqkv1 = (const float*)d_in[2];
    const float* Wqkv2 = (const float*)d_in[3];
    const float* Wout1 = (const float*)d_in[4];
    const float* Wout2 = (const float*)d_in[5];
    float* out = (float*)d_out;

    __half *s1, *s2, *xo, *yo, *hx, *hy, *hwq1, *hwq2, *hwo1, *hwo2;
    cudaGetSymbolAddress((void**)&s1, g_s1);
    cudaGetSymbolAddress((void**)&s2, g_s2);
    cudaGetSymbolAddress((void**)&xo, g_xo);
    cudaGetSymbolAddress((void**)&yo, g_yo);
    cudaGetSymbolAddress((void**)&hx, g_hx);
    cudaGetSymbolAddress((void**)&hy, g_hy);
    cudaGetSymbolAddress((void**)&hwq1, g_hwq1);
    cudaGetSymbolAddress((void**)&hwq2, g_hwq2);
    cudaGetSymbolAddress((void**)&hwo1, g_hwo1);
    cudaGetSymbolAddress((void**)&hwo2, g_hwo2);

    // Pre-convert all six inputs to fp16 (paired launches)
    const int n4_act = MTOK * EE / 4;
    const int n4_wq  = E3 * EE / 4;
    const int n4_wo  = EE * EE / 4;
    cvt_h_kernel<<<dim3((n4_act + 255) / 256, 2), 256>>>(
        (const float4*)x, (const float4*)y, (uint2*)hx, (uint2*)hy, n4_act);
    cvt_h_kernel<<<dim3((n4_wq + 255) / 256, 2), 256>>>(
        (const float4*)Wqkv1, (const float4*)Wqkv2, (uint2*)hwq1, (uint2*)hwq2, n4_wq);
    cvt_h_kernel<<<dim3((n4_wo + 255) / 256, 2), 256>>>(
        (const float4*)Wout1, (const float4*)Wout2, (uint2*)hwo1, (uint2*)hwo2, n4_wo);

    cudaFuncSetAttribute(gemm_f16_kernel<true>,
                         cudaFuncAttributeMaxDynamicSharedMemorySize, GSMEM_B);
    cudaFuncSetAttribute(gemm_f16_kernel<false>,
                         cudaFuncAttributeMaxDynamicSharedMemorySize, GSMEM_B);

    // QKV projections for BOTH streams (fp16 mma), fused split to [3][B][H][T][D]
    gemm_f16_kernel<true><<<dim3(E3 / BN, MTOK / BM, 2), 256, GSMEM_B>>>(
        hx, hy, hwq1, hwq2, s1, s2, E3);

    // Cross attention (fp16 mma flash)
    const int asmem = ASMW * 4;   // 55296 B
    cudaFuncSetAttribute(attn_tc_kernel,
                         cudaFuncAttributeMaxDynamicSharedMemorySize, asmem);
    attn_tc_kernel<<<dim3(TT / TQ, BBATCH * HH, 2), 128, asmem>>>(s1, s2, xo, yo);

    // Output projections for BOTH streams (fp16 mma, fp32 out)
    gemm_f16_kernel<false><<<dim3(EE / BN, MTOK / BM, 2), 256, GSMEM_B>>>(
        xo, yo, hwo1, hwo2, out, out + (size_t)MTOK * EE, EE);
}